// round 15
// baseline (speedup 1.0000x reference)
#include <cuda_runtime.h>
#include <cuda_bf16.h>
#include <math.h>
#include <stdint.h>

#define BB 2
#define CC 256
#define NN 4096
#define EPS_IN 1e-5f
#define EPS_NORM 1e-8f
#define SCALE 20.0f
#define PAD128(v) (((v) + 127) & ~127)

// ---------------- static scratch ----------------
__device__ float g_m[BB * NN];
__device__ int   g_qidx[BB * NN];
__device__ int   g_kidx[BB * NN];
__device__ int   g_nq[BB];
__device__ int   g_nk[BB];
__device__ float g_bufA[BB * CC * NN];   // conv out fp32
__device__ float g_bufB[BB * CC * NN];   // feat
__device__ float g_rn[BB * NN];
__device__ float g_Vc[BB * CC * NN];
__device__ float g_att[(long)BB * NN * NN];   // scores -> att in place (fp32)
__device__ float g_vis[BB * NN];
__device__ float g_vispart[BB * 32 * NN];
__device__ float g_maxv[1];

// bf16 split inputs for tensor-core convs
__device__ __nv_bfloat16 g_xh[BB * CC * NN];
__device__ __nv_bfloat16 g_xl[BB * CC * NN];
__device__ __nv_bfloat16 g_f1h[BB * CC * NN];
__device__ __nv_bfloat16 g_f1l[BB * CC * NN];
// packed conv weights: [chunk 16][kap 9][co 256][cipair-in-chunk 8] u32
#define WPK (16 * 9 * 256 * 8)
__device__ uint32_t g_w1h[WPK];
__device__ uint32_t g_w1l[WPK];
__device__ uint32_t g_w2h[WPK];
__device__ uint32_t g_w2l[WPK];

// packed Q/K/Xq: [b][cp 128][i 4096] u32 (pair along c)
__device__ uint32_t g_Qph[BB * 128 * NN];
__device__ uint32_t g_Qpl[BB * 128 * NN];
__device__ uint32_t g_Kph[BB * 128 * NN];
__device__ uint32_t g_Kpl[BB * 128 * NN];
__device__ uint32_t g_Xqph[BB * 128 * NN];
__device__ uint32_t g_Xqpl[BB * 128 * NN];
// packed AF (att_fore): [b][cp 128][i 4096]
__device__ uint32_t g_AFph[BB * 128 * NN];
__device__ uint32_t g_AFpl[BB * 128 * NN];
// packed fuse weights: [cp 256][co 256]
__device__ uint32_t g_WFh[256 * 256];
__device__ uint32_t g_WFl[256 * 256];

__device__ __forceinline__ float warpMax(float v) {
#pragma unroll
    for (int o = 16; o; o >>= 1) v = fmaxf(v, __shfl_xor_sync(0xffffffffu, v, o));
    return v;
}
__device__ __forceinline__ float warpSum(float v) {
#pragma unroll
    for (int o = 16; o; o >>= 1) v += __shfl_xor_sync(0xffffffffu, v, o);
    return v;
}

__device__ __forceinline__ void mma_bf16(float c[4], const uint32_t a[4],
                                         uint32_t b0, uint32_t b1) {
    asm volatile(
        "mma.sync.aligned.m16n8k16.row.col.f32.bf16.bf16.f32 "
        "{%0,%1,%2,%3}, {%4,%5,%6,%7}, {%8,%9}, {%0,%1,%2,%3};"
        : "+f"(c[0]), "+f"(c[1]), "+f"(c[2]), "+f"(c[3])
        : "r"(a[0]), "r"(a[1]), "r"(a[2]), "r"(a[3]), "r"(b0), "r"(b1));
}

__device__ __forceinline__ uint32_t pack2bf(float v0, float v1) {
    __nv_bfloat16 h0 = __float2bfloat16(v0);
    __nv_bfloat16 h1 = __float2bfloat16(v1);
    return (uint32_t)__bfloat16_as_ushort(h0) |
           ((uint32_t)__bfloat16_as_ushort(h1) << 16);
}
__device__ __forceinline__ uint32_t pack2bf_lo(float v0, float v1) {
    float h0 = __bfloat162float(__float2bfloat16(v0));
    float h1 = __bfloat162float(__float2bfloat16(v1));
    return pack2bf(v0 - h0, v1 - h1);
}

// ---------------- mask: MaxPool2d(8,8) > 0; also zero g_vis ---------------
__global__ void k_mask(const float* __restrict__ mask) {
    int gid = blockIdx.x * 256 + threadIdx.x;
    int b = gid >> 12;
    int j = gid & 4095;
    int py = j >> 6, px = j & 63;
    const float* mp = mask + (long)b * 262144 + (py * 8) * 512 + px * 8;
    float mx = 0.f;
#pragma unroll
    for (int dy = 0; dy < 8; dy++)
#pragma unroll
        for (int dx = 0; dx < 8; dx++) mx = fmaxf(mx, mp[dy * 512 + dx]);
    g_m[gid] = (mx > 0.f) ? 1.f : 0.f;
    g_vis[gid] = 0.f;
}

// ---------------- deterministic compaction --------------------------------
__global__ __launch_bounds__(256) void k_compact() {
    int b = blockIdx.x;
    int tid = threadIdx.x;
    __shared__ int wsum[8];
    __shared__ int baseq, basek;
    if (tid == 0) { baseq = 0; basek = 0; }
    __syncthreads();
    for (int chunk = 0; chunk < 16; chunk++) {
        int px = (chunk << 8) + tid;
        int vq = (g_m[(b << 12) + px] > 0.5f) ? 1 : 0;
        unsigned bal = __ballot_sync(0xffffffffu, vq);
        int lane = tid & 31, w = tid >> 5;
        int pre = __popc(bal & ((1u << lane) - 1u));
        if (lane == 0) wsum[w] = __popc(bal);
        __syncthreads();
        int woff = 0, tot = 0;
#pragma unroll
        for (int i = 0; i < 8; i++) {
            if (i < w) woff += wsum[i];
            tot += wsum[i];
        }
        int bq = baseq, bk = basek;
        int qbefore = woff + pre;
        if (vq) g_qidx[(b << 12) + bq + qbefore] = px;
        else    g_kidx[(b << 12) + bk + (tid - qbefore)] = px;
        __syncthreads();
        if (tid == 0) { baseq = bq + tot; basek = bk + (256 - tot); }
        __syncthreads();
    }
    if (tid == 0) { g_nq[b] = baseq; g_nk[b] = basek; }
}

// ---------------- pack conv weights ----------------------------------------
__global__ void k_packW(const float* __restrict__ w,
                        uint32_t* __restrict__ oh, uint32_t* __restrict__ ol) {
    int idx = blockIdx.x * 256 + threadIdx.x;   // < 294912
    int cpw = idx & 7;
    int co = (idx >> 3) & 255;
    int t = idx >> 11;
    int chunk = t / 9;
    int kap = t - chunk * 9;
    int cp = (chunk << 3) + cpw;
    float v0 = w[(co * 256 + 2 * cp) * 9 + kap];
    float v1 = w[(co * 256 + 2 * cp + 1) * 9 + kap];
    oh[idx] = pack2bf(v0, v1);
    ol[idx] = pack2bf_lo(v0, v1);
}

// ---------------- pack fuse weights: wf[co][512] -> [cp 256][co 256] -------
__global__ void k_packWF(const float* __restrict__ wf) {
    int idx = blockIdx.x * 256 + threadIdx.x;   // < 65536
    int cp = idx >> 8, co = idx & 255;
    float v0 = wf[co * 512 + 2 * cp];
    float v1 = wf[co * 512 + 2 * cp + 1];
    g_WFh[cp * 256 + co] = pack2bf(v0, v1);
    g_WFl[cp * 256 + co] = pack2bf_lo(v0, v1);
}

// ---------------- split x -> bf16 hi/lo ------------------------------------
__global__ void k_packX(const float* __restrict__ x,
                        __nv_bfloat16* __restrict__ xh,
                        __nv_bfloat16* __restrict__ xl) {
    int i = blockIdx.x * 256 + threadIdx.x;
    float v = x[i];
    __nv_bfloat16 h = __float2bfloat16(v);
    xh[i] = h;
    xl[i] = __float2bfloat16(v - __bfloat162float(h));
}

// ---------------- tensor-core conv3x3: implicit GEMM (R12 exact) ----------
__global__ __launch_bounds__(256) void k_conv_tc(const __nv_bfloat16* __restrict__ xh,
                                                 const __nv_bfloat16* __restrict__ xl,
                                                 const uint32_t* __restrict__ wph,
                                                 const uint32_t* __restrict__ wpl,
                                                 float* __restrict__ out) {
    extern __shared__ uint32_t dsm[];
    uint32_t* sAh = dsm;                 // 9*128*12 = 13824
    uint32_t* sAl = sAh + 13824;         // 9*128*8  = 9216
    uint32_t* sBh = sAl + 9216;          // 24 rows * 72
    uint32_t* sBl = sBh + 1728;

    int tid = threadIdx.x;
    int ytile = blockIdx.x;
    int co0 = blockIdx.y << 7;
    int b = blockIdx.z;
    int w = tid >> 5, l = tid & 31;
    int wm = w & 3, wn = w >> 2;
    int grp = l >> 2, tig = l & 3;

    float acc[2][4][4];
#pragma unroll
    for (int i = 0; i < 2; i++)
#pragma unroll
        for (int j = 0; j < 4; j++)
#pragma unroll
            for (int k = 0; k < 4; k++) acc[i][j][k] = 0.f;

    long xbase = (long)b * CC * NN;

    for (int chunk = 0; chunk < 16; chunk++) {
        int ci0 = chunk << 4;
        if (tid < 192) {
            int srow = tid >> 6;
            int rem = tid & 63;
            int pair = rem >> 3, cg = rem & 7;
            int gy = ytile - 1 + srow;
            int sb = (srow * 8 + pair) * 72 + 4 + (cg << 3);
            if ((unsigned)gy < 64u) {
                long e = xbase + (long)(ci0 + (pair << 1)) * NN + (gy << 6) + (cg << 3);
                long o = e + NN;
                uint4 ev = *(const uint4*)(xh + e);
                uint4 od = *(const uint4*)(xh + o);
                uint4 r0, r1;
                r0.x = __byte_perm(ev.x, od.x, 0x5410);
                r0.y = __byte_perm(ev.x, od.x, 0x7632);
                r0.z = __byte_perm(ev.y, od.y, 0x5410);
                r0.w = __byte_perm(ev.y, od.y, 0x7632);
                r1.x = __byte_perm(ev.z, od.z, 0x5410);
                r1.y = __byte_perm(ev.z, od.z, 0x7632);
                r1.z = __byte_perm(ev.w, od.w, 0x5410);
                r1.w = __byte_perm(ev.w, od.w, 0x7632);
                *(uint4*)&sBh[sb] = r0;
                *(uint4*)&sBh[sb + 4] = r1;
                ev = *(const uint4*)(xl + e);
                od = *(const uint4*)(xl + o);
                r0.x = __byte_perm(ev.x, od.x, 0x5410);
                r0.y = __byte_perm(ev.x, od.x, 0x7632);
                r0.z = __byte_perm(ev.y, od.y, 0x5410);
                r0.w = __byte_perm(ev.y, od.y, 0x7632);
                r1.x = __byte_perm(ev.z, od.z, 0x5410);
                r1.y = __byte_perm(ev.z, od.z, 0x7632);
                r1.z = __byte_perm(ev.w, od.w, 0x5410);
                r1.w = __byte_perm(ev.w, od.w, 0x7632);
                *(uint4*)&sBl[sb] = r0;
                *(uint4*)&sBl[sb + 4] = r1;
            } else {
                uint4 z = make_uint4(0, 0, 0, 0);
                *(uint4*)&sBh[sb] = z;
                *(uint4*)&sBh[sb + 4] = z;
                *(uint4*)&sBl[sb] = z;
                *(uint4*)&sBl[sb + 4] = z;
            }
        }
        if (tid >= 192 && tid < 240) {
            int t2 = tid - 192;
            int srow = t2 / 16, rem = t2 % 16;
            int pair = rem >> 1, edge = rem & 1;
            int off = (srow * 8 + pair) * 72 + (edge ? 68 : 3);
            sBh[off] = 0;
            sBl[off] = 0;
        }
        {
            long wb = (long)chunk * 9 * 2048;
            for (int idx = tid; idx < 2304; idx += 256) {
                int kap = idx >> 8;
                int rem = idx & 255;
                int row = rem >> 1, colh = (rem & 1) << 2;
                long g = wb + (long)kap * 2048 + ((long)(co0 + row) << 3) + colh;
                *(uint4*)&sAh[kap * 1536 + row * 12 + colh] =
                    *(const uint4*)(wph + g);
                *(uint4*)&sAl[kap * 1024 + (row << 3) + colh] =
                    *(const uint4*)(wpl + g);
            }
        }
        __syncthreads();

#pragma unroll
        for (int kap = 0; kap < 9; kap++) {
            int dy = kap / 3, dx = kap - dy * 3;
            uint32_t ah[2][4], al[2][4];
#pragma unroll
            for (int mf = 0; mf < 2; mf++) {
                int mr = (wm << 5) + (mf << 4);
                int abh = kap * 1536 + (mr + grp) * 12;
                int abl = kap * 1024 + ((mr + grp) << 3);
                ah[mf][0] = sAh[abh + tig];
                ah[mf][1] = sAh[abh + 96 + tig];
                ah[mf][2] = sAh[abh + tig + 4];
                ah[mf][3] = sAh[abh + 96 + tig + 4];
                al[mf][0] = sAl[abl + tig];
                al[mf][1] = sAl[abl + 64 + tig];
                al[mf][2] = sAl[abl + tig + 4];
                al[mf][3] = sAl[abl + 64 + tig + 4];
            }
#pragma unroll
            for (int nf = 0; nf < 4; nf++) {
                int n = (wn << 5) + (nf << 3) + grp;
                int a0 = (dy * 8 + tig) * 72 + n + dx + 3;
                uint32_t bh0 = sBh[a0];
                uint32_t bh1 = sBh[a0 + 288];
                uint32_t bl0 = sBl[a0];
                uint32_t bl1 = sBl[a0 + 288];
#pragma unroll
                for (int mf = 0; mf < 2; mf++) {
                    mma_bf16(acc[mf][nf], ah[mf], bh0, bh1);
                    mma_bf16(acc[mf][nf], ah[mf], bl0, bl1);
                    mma_bf16(acc[mf][nf], al[mf], bh0, bh1);
                }
            }
        }
        __syncthreads();
    }
#pragma unroll
    for (int mf = 0; mf < 2; mf++) {
        int r0 = co0 + (wm << 5) + (mf << 4) + grp;
#pragma unroll
        for (int nf = 0; nf < 4; nf++) {
            int p = (ytile << 6) + (wn << 5) + (nf << 3) + (tig << 1);
            *(float2*)&out[((long)(b * CC + r0) << 12) + p] =
                make_float2(acc[mf][nf][0], acc[mf][nf][1]);
            *(float2*)&out[((long)(b * CC + r0 + 8) << 12) + p] =
                make_float2(acc[mf][nf][2], acc[mf][nf][3]);
        }
    }
}

// ---------------- instance norm + relu -> bf16 split ----------------------
__global__ __launch_bounds__(256) void k_inorm0(const float* __restrict__ t,
                                                __nv_bfloat16* __restrict__ oh,
                                                __nv_bfloat16* __restrict__ ol) {
    long base = (long)blockIdx.x * NN;
    int tid = threadIdx.x;
    float s = 0.f, s2 = 0.f;
    for (int i = tid; i < NN; i += 256) {
        float v = t[base + i];
        s += v;
        s2 = fmaf(v, v, s2);
    }
    __shared__ float sh[16];
    __shared__ float smu, srs;
    s = warpSum(s);
    s2 = warpSum(s2);
    int wi = tid >> 5, l = tid & 31;
    if (l == 0) { sh[wi] = s; sh[8 + wi] = s2; }
    __syncthreads();
    if (tid == 0) {
        float a = 0.f, b2 = 0.f;
#pragma unroll
        for (int i = 0; i < 8; i++) { a += sh[i]; b2 += sh[8 + i]; }
        float mu = a * (1.f / NN);
        float var = b2 * (1.f / NN) - mu * mu;
        smu = mu;
        srs = rsqrtf(var + EPS_IN);
    }
    __syncthreads();
    float mu = smu, rs = srs;
    for (int i = tid; i < NN; i += 256) {
        float v = fmaxf((t[base + i] - mu) * rs, 0.f);
        __nv_bfloat16 h = __float2bfloat16(v);
        oh[base + i] = h;
        ol[base + i] = __float2bfloat16(v - __bfloat162float(h));
    }
}

// ---------------- instance norm + residual + relu -> fp32 -----------------
__global__ __launch_bounds__(256) void k_inorm1(const float* __restrict__ t,
                                                const float* __restrict__ xadd,
                                                float* __restrict__ o) {
    long base = (long)blockIdx.x * NN;
    int tid = threadIdx.x;
    float s = 0.f, s2 = 0.f;
    for (int i = tid; i < NN; i += 256) {
        float v = t[base + i];
        s += v;
        s2 = fmaf(v, v, s2);
    }
    __shared__ float sh[16];
    __shared__ float smu, srs;
    s = warpSum(s);
    s2 = warpSum(s2);
    int wi = tid >> 5, l = tid & 31;
    if (l == 0) { sh[wi] = s; sh[8 + wi] = s2; }
    __syncthreads();
    if (tid == 0) {
        float a = 0.f, b2 = 0.f;
#pragma unroll
        for (int i = 0; i < 8; i++) { a += sh[i]; b2 += sh[8 + i]; }
        float mu = a * (1.f / NN);
        float var = b2 * (1.f / NN) - mu * mu;
        smu = mu;
        srs = rsqrtf(var + EPS_IN);
    }
    __syncthreads();
    float mu = smu, rs = srs;
    for (int i = tid; i < NN; i += 256)
        o[base + i] = fmaxf((t[base + i] - mu) * rs + xadd[base + i], 0.f);
}

// ---------------- per-pixel channel L2 norm reciprocal --------------------
__global__ void k_rn(const float* __restrict__ feat) {
    int gid = blockIdx.x * 256 + threadIdx.x;
    int b = gid >> 12;
    int px = gid & 4095;
    const float* fb = feat + (long)b * CC * NN + px;
    float s = 0.f;
    for (int c = 0; c < CC; c++) {
        float f = fb[c << 12];
        s = fmaf(f, f, s);
    }
    g_rn[gid] = 1.f / (sqrtf(s) + EPS_NORM);
}

// ---------------- gather: packed Q/K (+packed Xq for queries, fp32 Vc) ----
__global__ __launch_bounds__(256) void k_gather(const float* __restrict__ feat,
                                                const float* __restrict__ x) {
    int b = blockIdx.z;
    int side = blockIdx.y;
    int i = (blockIdx.x << 8) + threadIdx.x;
    int n = side ? g_nk[b] : g_nq[b];
    int npad = PAD128(n);
    if (i >= npad) return;
    uint32_t* Ph = side ? g_Kph : g_Qph;
    uint32_t* Pl = side ? g_Kpl : g_Qpl;
    long off = (long)b * CC * NN;
    long poff = ((long)b << 19);
    if (i < n) {
        int px = side ? g_kidx[(b << 12) + i] : g_qidx[(b << 12) + i];
        float rn = g_rn[(b << 12) + px];
        const float* fb = feat + off + px;
        const float* xb = x + off + px;
        for (int c = 0; c < CC; c += 2) {
            float v0 = fb[c << 12] * rn;
            float v1 = fb[(c + 1) << 12] * rn;
            long pi = poff + ((long)(c >> 1) << 12) + i;
            Ph[pi] = pack2bf(v0, v1);
            Pl[pi] = pack2bf_lo(v0, v1);
            if (side) {
                g_Vc[off + (c << 12) + i] = xb[c << 12];
                g_Vc[off + ((c + 1) << 12) + i] = xb[(c + 1) << 12];
            } else {
                float u0 = xb[c << 12];
                float u1 = xb[(c + 1) << 12];
                g_Xqph[pi] = pack2bf(u0, u1);
                g_Xqpl[pi] = pack2bf_lo(u0, u1);
            }
        }
    } else {
        for (int c = 0; c < CC; c += 2) {
            long pi = poff + ((long)(c >> 1) << 12) + i;
            Ph[pi] = 0; Pl[pi] = 0;
            if (side) {
                g_Vc[off + (c << 12) + i] = 0.f;
                g_Vc[off + ((c + 1) << 12) + i] = 0.f;
            } else {
                g_Xqph[pi] = 0; g_Xqpl[pi] = 0;
            }
        }
    }
}

// ---------------- score GEMM tensor cores: 128q x 128k --------------------
__global__ __launch_bounds__(256) void k_score_tc(float* __restrict__ att) {
    int b = blockIdx.z;
    int q0 = blockIdx.y << 7;
    int k0 = blockIdx.x << 7;
    if (q0 >= PAD128(g_nq[b]) || k0 >= PAD128(g_nk[b])) return;
    __shared__ uint32_t sQh[128 * 9], sQl[128 * 9];
    __shared__ uint32_t sKh[8 * 136], sKl[8 * 136];
    int tid = threadIdx.x;
    int w = tid >> 5, l = tid & 31;
    int wm = w & 3, wn = w >> 2;
    int grp = l >> 2, tig = l & 3;
    int q = tid & 127, half = tid >> 7;
    long pbase = ((long)b << 19);

    float acc[2][8][4];
#pragma unroll
    for (int i = 0; i < 2; i++)
#pragma unroll
        for (int j = 0; j < 8; j++)
#pragma unroll
            for (int k = 0; k < 4; k++) acc[i][j][k] = 0.f;

    for (int step = 0; step < 16; step++) {
        int c0p = step << 3;
#pragma unroll
        for (int it = 0; it < 4; it++) {
            int cp = (it << 1) + half;
            long g = pbase + ((long)(c0p + cp) << 12);
            sQh[q * 9 + cp] = g_Qph[g + q0 + q];
            sQl[q * 9 + cp] = g_Qpl[g + q0 + q];
            sKh[cp * 136 + q] = g_Kph[g + k0 + q];
            sKl[cp * 136 + q] = g_Kpl[g + k0 + q];
        }
        __syncthreads();
        uint32_t ah[2][4], al[2][4];
#pragma unroll
        for (int mf = 0; mf < 2; mf++) {
            int ab = ((wm << 5) + (mf << 4) + grp) * 9;
            ah[mf][0] = sQh[ab + tig];
            ah[mf][1] = sQh[ab + 72 + tig];
            ah[mf][2] = sQh[ab + tig + 4];
            ah[mf][3] = sQh[ab + 72 + tig + 4];
            al[mf][0] = sQl[ab + tig];
            al[mf][1] = sQl[ab + 72 + tig];
            al[mf][2] = sQl[ab + tig + 4];
            al[mf][3] = sQl[ab + 72 + tig + 4];
        }
#pragma unroll
        for (int nf = 0; nf < 8; nf++) {
            int n = (wn << 6) + (nf << 3) + grp;
            uint32_t bh0 = sKh[tig * 136 + n];
            uint32_t bh1 = sKh[(tig + 4) * 136 + n];
            uint32_t bl0 = sKl[tig * 136 + n];
            uint32_t bl1 = sKl[(tig + 4) * 136 + n];
#pragma unroll
            for (int mf = 0; mf < 2; mf++) {
                mma_bf16(acc[mf][nf], ah[mf], bh0, bh1);
                mma_bf16(acc[mf][nf], ah[mf], bl0, bl1);
                mma_bf16(acc[mf][nf], al[mf], bh0, bh1);
            }
        }
        __syncthreads();
    }
    float* Cb = att + (long)b * NN * NN;
#pragma unroll
    for (int mf = 0; mf < 2; mf++) {
        int r0 = q0 + (wm << 5) + (mf << 4) + grp;
#pragma unroll
        for (int nf = 0; nf < 8; nf++) {
            int cc = k0 + (wn << 6) + (nf << 3) + (tig << 1);
            *(float2*)&Cb[(long)r0 * NN + cc] =
                make_float2(acc[mf][nf][0] * SCALE, acc[mf][nf][1] * SCALE);
            *(float2*)&Cb[(long)(r0 + 8) * NN + cc] =
                make_float2(acc[mf][nf][2] * SCALE, acc[mf][nf][3] * SCALE);
        }
    }
}

// ---------------- softmax in place (fp32, R4 exact) ------------------------
__global__ __launch_bounds__(256) void k_softmax(float* __restrict__ att) {
    int b = blockIdx.y;
    int i = blockIdx.x;
    int nq = g_nq[b];
    if (i >= nq) return;
    int nk = g_nk[b];
    int nkp = PAD128(nk);
    float* row = att + (long)b * NN * NN + (long)i * NN;
    int tid = threadIdx.x;
    float vals[16];
    float mx = -1e30f;
    int nt = (nkp + 255) >> 8;
#pragma unroll
    for (int t = 0; t < 16; t++) {
        if (t >= nt) break;
        int k = tid + (t << 8);
        float s = (k < nk) ? row[k] : -1e30f;
        vals[t] = s;
        mx = fmaxf(mx, s);
    }
    __shared__ float sh[8];
    __shared__ float bval;
    mx = warpMax(mx);
    int wi = tid >> 5, l = tid & 31;
    if (l == 0) sh[wi] = mx;
    __syncthreads();
    if (tid == 0) {
        float m2 = sh[0];
#pragma unroll
        for (int ii = 1; ii < 8; ii++) m2 = fmaxf(m2, sh[ii]);
        bval = m2;
    }
    __syncthreads();
    mx = bval;
    float sum = 0.f;
#pragma unroll
    for (int t = 0; t < 16; t++) {
        if (t >= nt) break;
        float e = __expf(vals[t] - mx);
        vals[t] = e;
        sum += e;
    }
    sum = warpSum(sum);
    __syncthreads();
    if (l == 0) sh[wi] = sum;
    __syncthreads();
    if (tid == 0) {
        float s2 = 0.f;
#pragma unroll
        for (int ii = 0; ii < 8; ii++) s2 += sh[ii];
        bval = 1.f / s2;
    }
    __syncthreads();
    float rinv = bval;
#pragma unroll
    for (int t = 0; t < 16; t++) {
        if (t >= nt) break;
        int k = tid + (t << 8);
        row[k] = (k < nk) ? vals[t] * rinv : 0.f;
    }
}

// ---------------- visatt stage1: coalesced partial column sums ------------
__global__ __launch_bounds__(256) void k_visatt1(const float* __restrict__ att) {
    int b = blockIdx.z;
    int qc = blockIdx.y;
    int k = (blockIdx.x << 8) + threadIdx.x;
    int nk = g_nk[b];
    if (k >= nk) return;
    int nq = g_nq[b];
    int q0 = qc << 7;
    if (q0 >= nq) { g_vispart[(((long)b * 32 + qc) << 12) + k] = 0.f; return; }
    int q1 = q0 + 128;
    if (q1 > nq) q1 = nq;
    const float* base = att + (long)b * NN * NN + k;
    float s = 0.f;
    for (int q = q0; q < q1; q++) s += base[(long)q << 12];
    g_vispart[(((long)b * 32 + qc) << 12) + k] = s;
}

// ---------------- visatt stage2: sum 32 partials, scatter ------------------
__global__ void k_visatt2() {
    int b = blockIdx.y;
    int k = blockIdx.x * 256 + threadIdx.x;
    int nk = g_nk[b];
    if (k >= nk) return;
    const float* part = g_vispart + (((long)b * 32) << 12) + k;
    float s = 0.f;
#pragma unroll
    for (int qc = 0; qc < 32; qc++) s += part[(long)qc << 12];
    g_vis[(b << 12) + g_kidx[(b << 12) + k]] = s;
}

// ---------------- AV GEMM: inline convert, epilogue writes packed AF -------
__global__ __launch_bounds__(256) void k_av_tc(const float* __restrict__ Vc,
                                               const float* __restrict__ att) {
    int b = blockIdx.z;
    int m0 = blockIdx.y << 7;
    int n0 = blockIdx.x << 7;
    if (n0 >= PAD128(g_nq[b])) return;
    int nkp = PAD128(g_nk[b]);
    __shared__ uint32_t sVh[128 * 9], sVl[128 * 9];
    __shared__ uint32_t sPh[8 * 136], sPl[8 * 136];
    int tid = threadIdx.x;
    int w = tid >> 5, l = tid & 31;
    int wm = w & 3, wn = w >> 2;
    int grp = l >> 2, tig = l & 3;
    int r8 = tid >> 3, c8 = tid & 7;

    float acc[2][8][4];
#pragma unroll
    for (int i = 0; i < 2; i++)
#pragma unroll
        for (int j = 0; j < 8; j++)
#pragma unroll
            for (int k = 0; k < 4; k++) acc[i][j][k] = 0.f;

    const float* Vb = Vc + (long)b * CC * NN;
    const float* Pb = att + (long)b * NN * NN;

    for (int jc = 0; jc < nkp; jc += 16) {
#pragma unroll
        for (int it = 0; it < 4; it++) {
            int rr = r8 + (it << 5);
            float2 v = *(const float2*)(Vb + (long)(m0 + rr) * NN + jc + (c8 << 1));
            sVh[rr * 9 + c8] = pack2bf(v.x, v.y);
            sVl[rr * 9 + c8] = pack2bf_lo(v.x, v.y);
            float2 p = *(const float2*)(Pb + (long)(n0 + rr) * NN + jc + (c8 << 1));
            sPh[c8 * 136 + rr] = pack2bf(p.x, p.y);
            sPl[c8 * 136 + rr] = pack2bf_lo(p.x, p.y);
        }
        __syncthreads();
        uint32_t ah[2][4], al[2][4];
#pragma unroll
        for (int mf = 0; mf < 2; mf++) {
            int ab = ((wm << 5) + (mf << 4) + grp) * 9;
            ah[mf][0] = sVh[ab + tig];
            ah[mf][1] = sVh[ab + 72 + tig];
            ah[mf][2] = sVh[ab + tig + 4];
            ah[mf][3] = sVh[ab + 72 + tig + 4];
            al[mf][0] = sVl[ab + tig];
            al[mf][1] = sVl[ab + 72 + tig];
            al[mf][2] = sVl[ab + tig + 4];
            al[mf][3] = sVl[ab + 72 + tig + 4];
        }
#pragma unroll
        for (int nf = 0; nf < 8; nf++) {
            int n = (wn << 6) + (nf << 3) + grp;
            uint32_t bh0 = sPh[tig * 136 + n];
            uint32_t bh1 = sPh[(tig + 4) * 136 + n];
            uint32_t bl0 = sPl[tig * 136 + n];
            uint32_t bl1 = sPl[(tig + 4) * 136 + n];
#pragma unroll
            for (int mf = 0; mf < 2; mf++) {
                mma_bf16(acc[mf][nf], ah[mf], bh0, bh1);
                mma_bf16(acc[mf][nf], ah[mf], bl0, bl1);
                mma_bf16(acc[mf][nf], al[mf], bh0, bh1);
            }
        }
        __syncthreads();
    }
    // epilogue: pack adjacent channel rows (grp pairs via shfl) -> AF
    long afbase = ((long)b << 19);
    int even = !(grp & 1);
#pragma unroll
    for (int mf = 0; mf < 2; mf++) {
        int r0 = m0 + (wm << 5) + (mf << 4) + grp;
#pragma unroll
        for (int nf = 0; nf < 8; nf++) {
            int cc = n0 + (wn << 6) + (nf << 3) + (tig << 1);
            float p0 = __shfl_xor_sync(0xffffffffu, acc[mf][nf][0], 4);
            float p1 = __shfl_xor_sync(0xffffffffu, acc[mf][nf][1], 4);
            float p2 = __shfl_xor_sync(0xffffffffu, acc[mf][nf][2], 4);
            float p3 = __shfl_xor_sync(0xffffffffu, acc[mf][nf][3], 4);
            if (even) {
                long o0 = afbase + ((long)(r0 >> 1) << 12) + cc;
                g_AFph[o0]     = pack2bf(acc[mf][nf][0], p0);
                g_AFph[o0 + 1] = pack2bf(acc[mf][nf][1], p1);
                g_AFpl[o0]     = pack2bf_lo(acc[mf][nf][0], p0);
                g_AFpl[o0 + 1] = pack2bf_lo(acc[mf][nf][1], p1);
                long o1 = afbase + ((long)((r0 >> 1) + 4) << 12) + cc;
                g_AFph[o1]     = pack2bf(acc[mf][nf][2], p2);
                g_AFph[o1 + 1] = pack2bf(acc[mf][nf][3], p3);
                g_AFpl[o1]     = pack2bf_lo(acc[mf][nf][2], p2);
                g_AFpl[o1 + 1] = pack2bf_lo(acc[mf][nf][3], p3);
            }
        }
    }
}

// ---------------- fuse GEMM tensor cores: K=512, scatter out --------------
__global__ __launch_bounds__(256) void k_fuse_tc(float* __restrict__ out) {
    int b = blockIdx.z;
    int m0 = blockIdx.y << 7;
    int n0 = blockIdx.x << 7;
    int nq = g_nq[b];
    if (n0 >= PAD128(nq)) return;
    __shared__ uint32_t sWh[128 * 9], sWl[128 * 9];
    __shared__ uint32_t sFh[8 * 136], sFl[8 * 136];
    int tid = threadIdx.x;
    int w = tid >> 5, l = tid & 31;
    int wm = w & 3, wn = w >> 2;
    int grp = l >> 2, tig = l & 3;
    int q = tid & 127, half = tid >> 7;
    long fbase = ((long)b << 19);

    float acc[2][8][4];
#pragma unroll
    for (int i = 0; i < 2; i++)
#pragma unroll
        for (int j = 0; j < 8; j++)
#pragma unroll
            for (int k = 0; k < 4; k++) acc[i][j][k] = 0.f;

    for (int step = 0; step < 32; step++) {
        int c0p = step << 3;
#pragma unroll
        for (int it = 0; it < 4; it++) {
            int cp = (it << 1) + half;
            int cpg = c0p + cp;
            sWh[q * 9 + cp] = g_WFh[cpg * 256 + m0 + q];
            sWl[q * 9 + cp] = g_WFl[cpg * 256 + m0 + q];
            const uint32_t* Fh = (cpg < 128) ? g_AFph : g_Xqph;
            const uint32_t* Fl = (cpg < 128) ? g_AFpl : g_Xqpl;
            long g = fbase + ((long)(cpg & 127) << 12);
            sFh[cp * 136 + q] = Fh[g + n0 + q];
            sFl[cp * 136 + q] = Fl[g + n0 + q];
        }
        __syncthreads();
        uint32_t ah[2][4], al[2][4];
#pragma unroll
        for (int mf = 0; mf < 2; mf++) {
            int ab = ((wm << 5) + (mf << 4) + grp) * 9;
            ah[mf][0] = sWh[ab + tig];
            ah[mf][1] = sWh[ab + 72 + tig];
            ah[mf][2] = sWh[ab + tig + 4];
            ah[mf][3] = sWh[ab + 72 + tig + 4];
            al[mf][0] = sWl[ab + tig];
            al[mf][1] = sWl[ab + 72 + tig];
            al[mf][2] = sWl[ab + tig + 4];
            al[mf][3] = sWl[ab + 72 + tig + 4];
        }
#pragma unroll
        for (int nf = 0; nf < 8; nf++) {
            int n = (wn << 6) + (nf << 3) + grp;
            uint32_t bh0 = sFh[tig * 136 + n];
            uint32_t bh1 = sFh[(tig + 4) * 136 + n];
            uint32_t bl0 = sFl[tig * 136 + n];
            uint32_t bl1 = sFl[(tig + 4) * 136 + n];
#pragma unroll
            for (int mf = 0; mf < 2; mf++) {
                mma_bf16(acc[mf][nf], ah[mf], bh0, bh1);
                mma_bf16(acc[mf][nf], ah[mf], bl0, bl1);
                mma_bf16(acc[mf][nf], al[mf], bh0, bh1);
            }
        }
        __syncthreads();
    }
    const int* qidx = g_qidx + (b << 12);
#pragma unroll
    for (int mf = 0; mf < 2; mf++) {
        int r0 = m0 + (wm << 5) + (mf << 4) + grp;
#pragma unroll
        for (int nf = 0; nf < 8; nf++) {
            int cc = n0 + (wn << 6) + (nf << 3) + (tig << 1);
            if (cc < nq) {
                int px = qidx[cc];
                out[((b * CC + r0) << 12) + px] = acc[mf][nf][0];
                out[((b * CC + r0 + 8) << 12) + px] = acc[mf][nf][2];
            }
            if (cc + 1 < nq) {
                int px = qidx[cc + 1];
                out[((b * CC + r0) << 12) + px] = acc[mf][nf][1];
                out[((b * CC + r0 + 8) << 12) + px] = acc[mf][nf][3];
            }
        }
    }
}

// ---------------- global max of visatt ----------------------------------
__global__ void k_vismax() {
    float mx = -1e30f;
    for (int i = threadIdx.x; i < BB * NN; i += 256) mx = fmaxf(mx, g_vis[i]);
    mx = warpMax(mx);
    __shared__ float sh[8];
    if ((threadIdx.x & 31) == 0) sh[threadIdx.x >> 5] = mx;
    __syncthreads();
    if (threadIdx.x == 0) {
        float m2 = sh[0];
#pragma unroll
        for (int i = 1; i < 8; i++) m2 = fmaxf(m2, sh[i]);
        g_maxv[0] = m2;
    }
}

// ---------------- attmask --------------------------------------------------
__global__ void k_attmask(float* __restrict__ o) {
    int i = blockIdx.x * 256 + threadIdx.x;
    int b = i >> 18;
    int r = i & 262143;
    int Y = r >> 9, X = r & 511;
    o[i] = g_vis[(b << 12) + ((Y >> 3) << 6) + (X >> 3)] / g_maxv[0];
}

// ---------------- launch -------------------------------------------------
extern "C" void kernel_launch(void* const* d_in, const int* in_sizes, int n_in,
                              void* d_out, int out_size) {
    const float* x = nullptr;
    const float* mask = nullptr;
    const float* w1 = nullptr;
    const float* w2 = nullptr;
    const float* wf = nullptr;
    int seen589 = 0;
    for (int i = 0; i < n_in; i++) {
        switch (in_sizes[i]) {
            case 2097152: x = (const float*)d_in[i]; break;
            case 524288:  mask = (const float*)d_in[i]; break;
            case 589824:
                if (seen589++ == 0) w1 = (const float*)d_in[i];
                else w2 = (const float*)d_in[i];
                break;
            case 131072:  wf = (const float*)d_in[i]; break;
            default: break;
        }
    }

    float *bufA, *bufB, *Vc, *att;
    __nv_bfloat16 *xh, *xl, *f1h, *f1l;
    uint32_t *w1h, *w1l, *w2h, *w2l;
    cudaGetSymbolAddress((void**)&bufA, g_bufA);
    cudaGetSymbolAddress((void**)&bufB, g_bufB);
    cudaGetSymbolAddress((void**)&Vc, g_Vc);
    cudaGetSymbolAddress((void**)&att, g_att);
    cudaGetSymbolAddress((void**)&xh, g_xh);
    cudaGetSymbolAddress((void**)&xl, g_xl);
    cudaGetSymbolAddress((void**)&f1h, g_f1h);
    cudaGetSymbolAddress((void**)&f1l, g_f1l);
    cudaGetSymbolAddress((void**)&w1h, g_w1h);
    cudaGetSymbolAddress((void**)&w1l, g_w1l);
    cudaGetSymbolAddress((void**)&w2h, g_w2h);
    cudaGetSymbolAddress((void**)&w2l, g_w2l);

    static cudaStream_t s1 = nullptr;
    static cudaEvent_t ev0 = nullptr, ev1 = nullptr, ev2 = nullptr, ev3 = nullptr;
    static int smem_set = 0;
    const int CONV_SMEM = (13824 + 9216 + 1728 * 2) * 4;   // 105984 B
    if (!smem_set) {
        cudaFuncSetAttribute(k_conv_tc, cudaFuncAttributeMaxDynamicSharedMemorySize,
                             CONV_SMEM);
        cudaStreamCreateWithFlags(&s1, cudaStreamNonBlocking);
        cudaEventCreateWithFlags(&ev0, cudaEventDisableTiming);
        cudaEventCreateWithFlags(&ev1, cudaEventDisableTiming);
        cudaEventCreateWithFlags(&ev2, cudaEventDisableTiming);
        cudaEventCreateWithFlags(&ev3, cudaEventDisableTiming);
        smem_set = 1;
    }

    float* out = (float*)d_out;
    float* attm = out + (long)BB * CC * NN;

    // fork: side stream does memcpy + weight/input packing
    cudaEventRecord(ev0, 0);
    cudaStreamWaitEvent(s1, ev0, 0);
    cudaMemcpyAsync(out, x, (size_t)BB * CC * NN * sizeof(float),
                    cudaMemcpyDeviceToDevice, s1);
    k_packW<<<1152, 256, 0, s1>>>(w1, w1h, w1l);
    k_packW<<<1152, 256, 0, s1>>>(w2, w2h, w2l);
    k_packWF<<<256, 256, 0, s1>>>(wf);
    k_packX<<<8192, 256, 0, s1>>>(x, xh, xl);
    cudaEventRecord(ev1, s1);

    // main stream: mask/compact concurrently with the packing above
    k_mask<<<32, 256>>>(mask);
    k_compact<<<BB, 256>>>();
    cudaStreamWaitEvent(0, ev1, 0);

    k_conv_tc<<<dim3(64, 2, BB), 256, CONV_SMEM>>>(xh, xl, w1h, w1l, bufA);
    k_inorm0<<<BB * CC, 256>>>(bufA, f1h, f1l);
    k_conv_tc<<<dim3(64, 2, BB), 256, CONV_SMEM>>>(f1h, f1l, w2h, w2l, bufA);
    k_inorm1<<<BB * CC, 256>>>(bufA, x, bufB);            // bufB = feat
    k_rn<<<32, 256>>>(bufB);
    k_gather<<<dim3(16, 2, BB), 256>>>(bufB, x);          // Qp, Kp, Xqp, Vc
    k_score_tc<<<dim3(32, 32, BB), 256>>>(att);
    k_softmax<<<dim3(4096, BB), 256>>>(att);              // in-place fp32

    // fork: visatt chain + attmask on side stream, concurrent with av/fuse
    cudaEventRecord(ev2, 0);
    cudaStreamWaitEvent(s1, ev2, 0);
    k_visatt1<<<dim3(8, 32, BB), 256, 0, s1>>>(att);
    k_visatt2<<<dim3(8, BB), 256, 0, s1>>>();
    k_vismax<<<1, 256, 0, s1>>>();
    k_attmask<<<2048, 256, 0, s1>>>(attm);
    cudaEventRecord(ev3, s1);

    k_av_tc<<<dim3(32, 2, BB), 256>>>(Vc, att);           // writes packed AF
    k_fuse_tc<<<dim3(32, 2, BB), 256>>>(out);

    // join: attmask must complete before capture ends
    cudaStreamWaitEvent(0, ev3, 0);
}

// round 16
// speedup vs baseline: 1.0140x; 1.0140x over previous
#include <cuda_runtime.h>
#include <cuda_bf16.h>
#include <math.h>
#include <stdint.h>

#define BB 2
#define CC 256
#define NN 4096
#define EPS_IN 1e-5f
#define EPS_NORM 1e-8f
#define SCALE 20.0f
#define PAD128(v) (((v) + 127) & ~127)

// ---------------- static scratch ----------------
__device__ float g_m[BB * NN];
__device__ int   g_qidx[BB * NN];
__device__ int   g_kidx[BB * NN];
__device__ int   g_nq[BB];
__device__ int   g_nk[BB];
__device__ float g_bufA[BB * CC * NN];   // conv out fp32 / att_fore
__device__ float g_bufB[BB * CC * NN];   // feat
__device__ float g_rn[BB * NN];
__device__ float g_Vc[BB * CC * NN];
__device__ float g_att[(long)BB * NN * NN];   // scores -> att in place (fp32)
__device__ float g_vis[BB * NN];
__device__ float g_vispart[BB * 32 * NN];
__device__ float g_maxv[1];

// bf16 split inputs for tensor-core convs
__device__ __nv_bfloat16 g_xh[BB * CC * NN];
__device__ __nv_bfloat16 g_xl[BB * CC * NN];
__device__ __nv_bfloat16 g_f1h[BB * CC * NN];
__device__ __nv_bfloat16 g_f1l[BB * CC * NN];
// packed conv weights: [chunk 16][kap 9][co 256][cipair-in-chunk 8] u32
#define WPK (16 * 9 * 256 * 8)
__device__ uint32_t g_w1h[WPK];
__device__ uint32_t g_w1l[WPK];
__device__ uint32_t g_w2h[WPK];
__device__ uint32_t g_w2l[WPK];

// packed Q/K/Xq: [b][cp 128][i 4096] u32 (pair along c)
__device__ uint32_t g_Qph[BB * 128 * NN];
__device__ uint32_t g_Qpl[BB * 128 * NN];
__device__ uint32_t g_Kph[BB * 128 * NN];
__device__ uint32_t g_Kpl[BB * 128 * NN];
__device__ uint32_t g_Xqph[BB * 128 * NN];
__device__ uint32_t g_Xqpl[BB * 128 * NN];
// packed AF (att_fore): [b][cp 128][i 4096]
__device__ uint32_t g_AFph[BB * 128 * NN];
__device__ uint32_t g_AFpl[BB * 128 * NN];
// packed fuse weights: [cp 256][co 256]
__device__ uint32_t g_WFh[256 * 256];
__device__ uint32_t g_WFl[256 * 256];

__device__ __forceinline__ float warpMax(float v) {
#pragma unroll
    for (int o = 16; o; o >>= 1) v = fmaxf(v, __shfl_xor_sync(0xffffffffu, v, o));
    return v;
}
__device__ __forceinline__ float warpSum(float v) {
#pragma unroll
    for (int o = 16; o; o >>= 1) v += __shfl_xor_sync(0xffffffffu, v, o);
    return v;
}

__device__ __forceinline__ void mma_bf16(float c[4], const uint32_t a[4],
                                         uint32_t b0, uint32_t b1) {
    asm volatile(
        "mma.sync.aligned.m16n8k16.row.col.f32.bf16.bf16.f32 "
        "{%0,%1,%2,%3}, {%4,%5,%6,%7}, {%8,%9}, {%0,%1,%2,%3};"
        : "+f"(c[0]), "+f"(c[1]), "+f"(c[2]), "+f"(c[3])
        : "r"(a[0]), "r"(a[1]), "r"(a[2]), "r"(a[3]), "r"(b0), "r"(b1));
}

__device__ __forceinline__ uint32_t pack2bf(float v0, float v1) {
    __nv_bfloat16 h0 = __float2bfloat16(v0);
    __nv_bfloat16 h1 = __float2bfloat16(v1);
    return (uint32_t)__bfloat16_as_ushort(h0) |
           ((uint32_t)__bfloat16_as_ushort(h1) << 16);
}
__device__ __forceinline__ uint32_t pack2bf_lo(float v0, float v1) {
    float h0 = __bfloat162float(__float2bfloat16(v0));
    float h1 = __bfloat162float(__float2bfloat16(v1));
    return pack2bf(v0 - h0, v1 - h1);
}

// ---------------- mask: MaxPool2d(8,8) > 0; also zero g_vis ---------------
__global__ void k_mask(const float* __restrict__ mask) {
    int gid = blockIdx.x * 256 + threadIdx.x;
    int b = gid >> 12;
    int j = gid & 4095;
    int py = j >> 6, px = j & 63;
    const float* mp = mask + (long)b * 262144 + (py * 8) * 512 + px * 8;
    float mx = 0.f;
#pragma unroll
    for (int dy = 0; dy < 8; dy++)
#pragma unroll
        for (int dx = 0; dx < 8; dx++) mx = fmaxf(mx, mp[dy * 512 + dx]);
    g_m[gid] = (mx > 0.f) ? 1.f : 0.f;
    g_vis[gid] = 0.f;
}

// ---------------- deterministic compaction --------------------------------
__global__ __launch_bounds__(256) void k_compact() {
    int b = blockIdx.x;
    int tid = threadIdx.x;
    __shared__ int wsum[8];
    __shared__ int baseq, basek;
    if (tid == 0) { baseq = 0; basek = 0; }
    __syncthreads();
    for (int chunk = 0; chunk < 16; chunk++) {
        int px = (chunk << 8) + tid;
        int vq = (g_m[(b << 12) + px] > 0.5f) ? 1 : 0;
        unsigned bal = __ballot_sync(0xffffffffu, vq);
        int lane = tid & 31, w = tid >> 5;
        int pre = __popc(bal & ((1u << lane) - 1u));
        if (lane == 0) wsum[w] = __popc(bal);
        __syncthreads();
        int woff = 0, tot = 0;
#pragma unroll
        for (int i = 0; i < 8; i++) {
            if (i < w) woff += wsum[i];
            tot += wsum[i];
        }
        int bq = baseq, bk = basek;
        int qbefore = woff + pre;
        if (vq) g_qidx[(b << 12) + bq + qbefore] = px;
        else    g_kidx[(b << 12) + bk + (tid - qbefore)] = px;
        __syncthreads();
        if (tid == 0) { baseq = bq + tot; basek = bk + (256 - tot); }
        __syncthreads();
    }
    if (tid == 0) { g_nq[b] = baseq; g_nk[b] = basek; }
}

// ---------------- pack conv weights ----------------------------------------
__global__ void k_packW(const float* __restrict__ w,
                        uint32_t* __restrict__ oh, uint32_t* __restrict__ ol) {
    int idx = blockIdx.x * 256 + threadIdx.x;   // < 294912
    int cpw = idx & 7;
    int co = (idx >> 3) & 255;
    int t = idx >> 11;
    int chunk = t / 9;
    int kap = t - chunk * 9;
    int cp = (chunk << 3) + cpw;
    float v0 = w[(co * 256 + 2 * cp) * 9 + kap];
    float v1 = w[(co * 256 + 2 * cp + 1) * 9 + kap];
    oh[idx] = pack2bf(v0, v1);
    ol[idx] = pack2bf_lo(v0, v1);
}

// ---------------- pack fuse weights: wf[co][512] -> [cp 256][co 256] -------
__global__ void k_packWF(const float* __restrict__ wf) {
    int idx = blockIdx.x * 256 + threadIdx.x;   // < 65536
    int cp = idx >> 8, co = idx & 255;
    float v0 = wf[co * 512 + 2 * cp];
    float v1 = wf[co * 512 + 2 * cp + 1];
    g_WFh[cp * 256 + co] = pack2bf(v0, v1);
    g_WFl[cp * 256 + co] = pack2bf_lo(v0, v1);
}

// ---------------- split x -> bf16 hi/lo ------------------------------------
__global__ void k_packX(const float* __restrict__ x,
                        __nv_bfloat16* __restrict__ xh,
                        __nv_bfloat16* __restrict__ xl) {
    int i = blockIdx.x * 256 + threadIdx.x;
    float v = x[i];
    __nv_bfloat16 h = __float2bfloat16(v);
    xh[i] = h;
    xl[i] = __float2bfloat16(v - __bfloat162float(h));
}

// ---------------- tensor-core conv3x3: implicit GEMM (R12 exact) ----------
__global__ __launch_bounds__(256) void k_conv_tc(const __nv_bfloat16* __restrict__ xh,
                                                 const __nv_bfloat16* __restrict__ xl,
                                                 const uint32_t* __restrict__ wph,
                                                 const uint32_t* __restrict__ wpl,
                                                 float* __restrict__ out) {
    extern __shared__ uint32_t dsm[];
    uint32_t* sAh = dsm;                 // 9*128*12 = 13824
    uint32_t* sAl = sAh + 13824;         // 9*128*8  = 9216
    uint32_t* sBh = sAl + 9216;          // 24 rows * 72
    uint32_t* sBl = sBh + 1728;

    int tid = threadIdx.x;
    int ytile = blockIdx.x;
    int co0 = blockIdx.y << 7;
    int b = blockIdx.z;
    int w = tid >> 5, l = tid & 31;
    int wm = w & 3, wn = w >> 2;
    int grp = l >> 2, tig = l & 3;

    float acc[2][4][4];
#pragma unroll
    for (int i = 0; i < 2; i++)
#pragma unroll
        for (int j = 0; j < 4; j++)
#pragma unroll
            for (int k = 0; k < 4; k++) acc[i][j][k] = 0.f;

    long xbase = (long)b * CC * NN;

    for (int chunk = 0; chunk < 16; chunk++) {
        int ci0 = chunk << 4;
        if (tid < 192) {
            int srow = tid >> 6;
            int rem = tid & 63;
            int pair = rem >> 3, cg = rem & 7;
            int gy = ytile - 1 + srow;
            int sb = (srow * 8 + pair) * 72 + 4 + (cg << 3);
            if ((unsigned)gy < 64u) {
                long e = xbase + (long)(ci0 + (pair << 1)) * NN + (gy << 6) + (cg << 3);
                long o = e + NN;
                uint4 ev = *(const uint4*)(xh + e);
                uint4 od = *(const uint4*)(xh + o);
                uint4 r0, r1;
                r0.x = __byte_perm(ev.x, od.x, 0x5410);
                r0.y = __byte_perm(ev.x, od.x, 0x7632);
                r0.z = __byte_perm(ev.y, od.y, 0x5410);
                r0.w = __byte_perm(ev.y, od.y, 0x7632);
                r1.x = __byte_perm(ev.z, od.z, 0x5410);
                r1.y = __byte_perm(ev.z, od.z, 0x7632);
                r1.z = __byte_perm(ev.w, od.w, 0x5410);
                r1.w = __byte_perm(ev.w, od.w, 0x7632);
                *(uint4*)&sBh[sb] = r0;
                *(uint4*)&sBh[sb + 4] = r1;
                ev = *(const uint4*)(xl + e);
                od = *(const uint4*)(xl + o);
                r0.x = __byte_perm(ev.x, od.x, 0x5410);
                r0.y = __byte_perm(ev.x, od.x, 0x7632);
                r0.z = __byte_perm(ev.y, od.y, 0x5410);
                r0.w = __byte_perm(ev.y, od.y, 0x7632);
                r1.x = __byte_perm(ev.z, od.z, 0x5410);
                r1.y = __byte_perm(ev.z, od.z, 0x7632);
                r1.z = __byte_perm(ev.w, od.w, 0x5410);
                r1.w = __byte_perm(ev.w, od.w, 0x7632);
                *(uint4*)&sBl[sb] = r0;
                *(uint4*)&sBl[sb + 4] = r1;
            } else {
                uint4 z = make_uint4(0, 0, 0, 0);
                *(uint4*)&sBh[sb] = z;
                *(uint4*)&sBh[sb + 4] = z;
                *(uint4*)&sBl[sb] = z;
                *(uint4*)&sBl[sb + 4] = z;
            }
        }
        if (tid >= 192 && tid < 240) {
            int t2 = tid - 192;
            int srow = t2 / 16, rem = t2 % 16;
            int pair = rem >> 1, edge = rem & 1;
            int off = (srow * 8 + pair) * 72 + (edge ? 68 : 3);
            sBh[off] = 0;
            sBl[off] = 0;
        }
        {
            long wb = (long)chunk * 9 * 2048;
            for (int idx = tid; idx < 2304; idx += 256) {
                int kap = idx >> 8;
                int rem = idx & 255;
                int row = rem >> 1, colh = (rem & 1) << 2;
                long g = wb + (long)kap * 2048 + ((long)(co0 + row) << 3) + colh;
                *(uint4*)&sAh[kap * 1536 + row * 12 + colh] =
                    *(const uint4*)(wph + g);
                *(uint4*)&sAl[kap * 1024 + (row << 3) + colh] =
                    *(const uint4*)(wpl + g);
            }
        }
        __syncthreads();

#pragma unroll
        for (int kap = 0; kap < 9; kap++) {
            int dy = kap / 3, dx = kap - dy * 3;
            uint32_t ah[2][4], al[2][4];
#pragma unroll
            for (int mf = 0; mf < 2; mf++) {
                int mr = (wm << 5) + (mf << 4);
                int abh = kap * 1536 + (mr + grp) * 12;
                int abl = kap * 1024 + ((mr + grp) << 3);
                ah[mf][0] = sAh[abh + tig];
                ah[mf][1] = sAh[abh + 96 + tig];
                ah[mf][2] = sAh[abh + tig + 4];
                ah[mf][3] = sAh[abh + 96 + tig + 4];
                al[mf][0] = sAl[abl + tig];
                al[mf][1] = sAl[abl + 64 + tig];
                al[mf][2] = sAl[abl + tig + 4];
                al[mf][3] = sAl[abl + 64 + tig + 4];
            }
#pragma unroll
            for (int nf = 0; nf < 4; nf++) {
                int n = (wn << 5) + (nf << 3) + grp;
                int a0 = (dy * 8 + tig) * 72 + n + dx + 3;
                uint32_t bh0 = sBh[a0];
                uint32_t bh1 = sBh[a0 + 288];
                uint32_t bl0 = sBl[a0];
                uint32_t bl1 = sBl[a0 + 288];
#pragma unroll
                for (int mf = 0; mf < 2; mf++) {
                    mma_bf16(acc[mf][nf], ah[mf], bh0, bh1);
                    mma_bf16(acc[mf][nf], ah[mf], bl0, bl1);
                    mma_bf16(acc[mf][nf], al[mf], bh0, bh1);
                }
            }
        }
        __syncthreads();
    }
#pragma unroll
    for (int mf = 0; mf < 2; mf++) {
        int r0 = co0 + (wm << 5) + (mf << 4) + grp;
#pragma unroll
        for (int nf = 0; nf < 4; nf++) {
            int p = (ytile << 6) + (wn << 5) + (nf << 3) + (tig << 1);
            *(float2*)&out[((long)(b * CC + r0) << 12) + p] =
                make_float2(acc[mf][nf][0], acc[mf][nf][1]);
            *(float2*)&out[((long)(b * CC + r0 + 8) << 12) + p] =
                make_float2(acc[mf][nf][2], acc[mf][nf][3]);
        }
    }
}

// ---------------- instance norm + relu -> bf16 split ----------------------
__global__ __launch_bounds__(256) void k_inorm0(const float* __restrict__ t,
                                                __nv_bfloat16* __restrict__ oh,
                                                __nv_bfloat16* __restrict__ ol) {
    long base = (long)blockIdx.x * NN;
    int tid = threadIdx.x;
    float s = 0.f, s2 = 0.f;
    for (int i = tid; i < NN; i += 256) {
        float v = t[base + i];
        s += v;
        s2 = fmaf(v, v, s2);
    }
    __shared__ float sh[16];
    __shared__ float smu, srs;
    s = warpSum(s);
    s2 = warpSum(s2);
    int wi = tid >> 5, l = tid & 31;
    if (l == 0) { sh[wi] = s; sh[8 + wi] = s2; }
    __syncthreads();
    if (tid == 0) {
        float a = 0.f, b2 = 0.f;
#pragma unroll
        for (int i = 0; i < 8; i++) { a += sh[i]; b2 += sh[8 + i]; }
        float mu = a * (1.f / NN);
        float var = b2 * (1.f / NN) - mu * mu;
        smu = mu;
        srs = rsqrtf(var + EPS_IN);
    }
    __syncthreads();
    float mu = smu, rs = srs;
    for (int i = tid; i < NN; i += 256) {
        float v = fmaxf((t[base + i] - mu) * rs, 0.f);
        __nv_bfloat16 h = __float2bfloat16(v);
        oh[base + i] = h;
        ol[base + i] = __float2bfloat16(v - __bfloat162float(h));
    }
}

// ---------------- instance norm + residual + relu -> fp32 -----------------
__global__ __launch_bounds__(256) void k_inorm1(const float* __restrict__ t,
                                                const float* __restrict__ xadd,
                                                float* __restrict__ o) {
    long base = (long)blockIdx.x * NN;
    int tid = threadIdx.x;
    float s = 0.f, s2 = 0.f;
    for (int i = tid; i < NN; i += 256) {
        float v = t[base + i];
        s += v;
        s2 = fmaf(v, v, s2);
    }
    __shared__ float sh[16];
    __shared__ float smu, srs;
    s = warpSum(s);
    s2 = warpSum(s2);
    int wi = tid >> 5, l = tid & 31;
    if (l == 0) { sh[wi] = s; sh[8 + wi] = s2; }
    __syncthreads();
    if (tid == 0) {
        float a = 0.f, b2 = 0.f;
#pragma unroll
        for (int i = 0; i < 8; i++) { a += sh[i]; b2 += sh[8 + i]; }
        float mu = a * (1.f / NN);
        float var = b2 * (1.f / NN) - mu * mu;
        smu = mu;
        srs = rsqrtf(var + EPS_IN);
    }
    __syncthreads();
    float mu = smu, rs = srs;
    for (int i = tid; i < NN; i += 256)
        o[base + i] = fmaxf((t[base + i] - mu) * rs + xadd[base + i], 0.f);
}

// ---------------- per-pixel channel L2 norm reciprocal --------------------
__global__ void k_rn(const float* __restrict__ feat) {
    int gid = blockIdx.x * 256 + threadIdx.x;
    int b = gid >> 12;
    int px = gid & 4095;
    const float* fb = feat + (long)b * CC * NN + px;
    float s = 0.f;
    for (int c = 0; c < CC; c++) {
        float f = fb[c << 12];
        s = fmaf(f, f, s);
    }
    g_rn[gid] = 1.f / (sqrtf(s) + EPS_NORM);
}

// ---------------- gather: packed Q/K (+packed Xq for queries, fp32 Vc) ----
__global__ __launch_bounds__(256) void k_gather(const float* __restrict__ feat,
                                                const float* __restrict__ x) {
    int b = blockIdx.z;
    int side = blockIdx.y;
    int i = (blockIdx.x << 8) + threadIdx.x;
    int n = side ? g_nk[b] : g_nq[b];
    int npad = PAD128(n);
    if (i >= npad) return;
    uint32_t* Ph = side ? g_Kph : g_Qph;
    uint32_t* Pl = side ? g_Kpl : g_Qpl;
    long off = (long)b * CC * NN;
    long poff = ((long)b << 19);
    if (i < n) {
        int px = side ? g_kidx[(b << 12) + i] : g_qidx[(b << 12) + i];
        float rn = g_rn[(b << 12) + px];
        const float* fb = feat + off + px;
        const float* xb = x + off + px;
        for (int c = 0; c < CC; c += 2) {
            float v0 = fb[c << 12] * rn;
            float v1 = fb[(c + 1) << 12] * rn;
            long pi = poff + ((long)(c >> 1) << 12) + i;
            Ph[pi] = pack2bf(v0, v1);
            Pl[pi] = pack2bf_lo(v0, v1);
            if (side) {
                g_Vc[off + (c << 12) + i] = xb[c << 12];
                g_Vc[off + ((c + 1) << 12) + i] = xb[(c + 1) << 12];
            } else {
                float u0 = xb[c << 12];
                float u1 = xb[(c + 1) << 12];
                g_Xqph[pi] = pack2bf(u0, u1);
                g_Xqpl[pi] = pack2bf_lo(u0, u1);
            }
        }
    } else {
        for (int c = 0; c < CC; c += 2) {
            long pi = poff + ((long)(c >> 1) << 12) + i;
            Ph[pi] = 0; Pl[pi] = 0;
            if (side) {
                g_Vc[off + (c << 12) + i] = 0.f;
                g_Vc[off + ((c + 1) << 12) + i] = 0.f;
            } else {
                g_Xqph[pi] = 0; g_Xqpl[pi] = 0;
            }
        }
    }
}

// ---------------- score GEMM tensor cores: 128q x 128k --------------------
__global__ __launch_bounds__(256) void k_score_tc(float* __restrict__ att) {
    int b = blockIdx.z;
    int q0 = blockIdx.y << 7;
    int k0 = blockIdx.x << 7;
    if (q0 >= PAD128(g_nq[b]) || k0 >= PAD128(g_nk[b])) return;
    __shared__ uint32_t sQh[128 * 9], sQl[128 * 9];
    __shared__ uint32_t sKh[8 * 136], sKl[8 * 136];
    int tid = threadIdx.x;
    int w = tid >> 5, l = tid & 31;
    int wm = w & 3, wn = w >> 2;
    int grp = l >> 2, tig = l & 3;
    int q = tid & 127, half = tid >> 7;
    long pbase = ((long)b << 19);

    float acc[2][8][4];
#pragma unroll
    for (int i = 0; i < 2; i++)
#pragma unroll
        for (int j = 0; j < 8; j++)
#pragma unroll
            for (int k = 0; k < 4; k++) acc[i][j][k] = 0.f;

    for (int step = 0; step < 16; step++) {
        int c0p = step << 3;
#pragma unroll
        for (int it = 0; it < 4; it++) {
            int cp = (it << 1) + half;
            long g = pbase + ((long)(c0p + cp) << 12);
            sQh[q * 9 + cp] = g_Qph[g + q0 + q];
            sQl[q * 9 + cp] = g_Qpl[g + q0 + q];
            sKh[cp * 136 + q] = g_Kph[g + k0 + q];
            sKl[cp * 136 + q] = g_Kpl[g + k0 + q];
        }
        __syncthreads();
        uint32_t ah[2][4], al[2][4];
#pragma unroll
        for (int mf = 0; mf < 2; mf++) {
            int ab = ((wm << 5) + (mf << 4) + grp) * 9;
            ah[mf][0] = sQh[ab + tig];
            ah[mf][1] = sQh[ab + 72 + tig];
            ah[mf][2] = sQh[ab + tig + 4];
            ah[mf][3] = sQh[ab + 72 + tig + 4];
            al[mf][0] = sQl[ab + tig];
            al[mf][1] = sQl[ab + 72 + tig];
            al[mf][2] = sQl[ab + tig + 4];
            al[mf][3] = sQl[ab + 72 + tig + 4];
        }
#pragma unroll
        for (int nf = 0; nf < 8; nf++) {
            int n = (wn << 6) + (nf << 3) + grp;
            uint32_t bh0 = sKh[tig * 136 + n];
            uint32_t bh1 = sKh[(tig + 4) * 136 + n];
            uint32_t bl0 = sKl[tig * 136 + n];
            uint32_t bl1 = sKl[(tig + 4) * 136 + n];
#pragma unroll
            for (int mf = 0; mf < 2; mf++) {
                mma_bf16(acc[mf][nf], ah[mf], bh0, bh1);
                mma_bf16(acc[mf][nf], ah[mf], bl0, bl1);
                mma_bf16(acc[mf][nf], al[mf], bh0, bh1);
            }
        }
        __syncthreads();
    }
    float* Cb = att + (long)b * NN * NN;
#pragma unroll
    for (int mf = 0; mf < 2; mf++) {
        int r0 = q0 + (wm << 5) + (mf << 4) + grp;
#pragma unroll
        for (int nf = 0; nf < 8; nf++) {
            int cc = k0 + (wn << 6) + (nf << 3) + (tig << 1);
            *(float2*)&Cb[(long)r0 * NN + cc] =
                make_float2(acc[mf][nf][0] * SCALE, acc[mf][nf][1] * SCALE);
            *(float2*)&Cb[(long)(r0 + 8) * NN + cc] =
                make_float2(acc[mf][nf][2] * SCALE, acc[mf][nf][3] * SCALE);
        }
    }
}

// ---------------- softmax in place (fp32, R4 exact) ------------------------
__global__ __launch_bounds__(256) void k_softmax(float* __restrict__ att) {
    int b = blockIdx.y;
    int i = blockIdx.x;
    int nq = g_nq[b];
    if (i >= nq) return;
    int nk = g_nk[b];
    int nkp = PAD128(nk);
    float* row = att + (long)b * NN * NN + (long)i * NN;
    int tid = threadIdx.x;
    float vals[16];
    float mx = -1e30f;
    int nt = (nkp + 255) >> 8;
#pragma unroll
    for (int t = 0; t < 16; t++) {
        if (t >= nt) break;
        int k = tid + (t << 8);
        float s = (k < nk) ? row[k] : -1e30f;
        vals[t] = s;
        mx = fmaxf(mx, s);
    }
    __shared__ float sh[8];
    __shared__ float bval;
    mx = warpMax(mx);
    int wi = tid >> 5, l = tid & 31;
    if (l == 0) sh[wi] = mx;
    __syncthreads();
    if (tid == 0) {
        float m2 = sh[0];
#pragma unroll
        for (int ii = 1; ii < 8; ii++) m2 = fmaxf(m2, sh[ii]);
        bval = m2;
    }
    __syncthreads();
    mx = bval;
    float sum = 0.f;
#pragma unroll
    for (int t = 0; t < 16; t++) {
        if (t >= nt) break;
        float e = __expf(vals[t] - mx);
        vals[t] = e;
        sum += e;
    }
    sum = warpSum(sum);
    __syncthreads();
    if (l == 0) sh[wi] = sum;
    __syncthreads();
    if (tid == 0) {
        float s2 = 0.f;
#pragma unroll
        for (int ii = 0; ii < 8; ii++) s2 += sh[ii];
        bval = 1.f / s2;
    }
    __syncthreads();
    float rinv = bval;
#pragma unroll
    for (int t = 0; t < 16; t++) {
        if (t >= nt) break;
        int k = tid + (t << 8);
        row[k] = (k < nk) ? vals[t] * rinv : 0.f;
    }
}

// ---------------- visatt stage1: coalesced partial column sums ------------
__global__ __launch_bounds__(256) void k_visatt1(const float* __restrict__ att) {
    int b = blockIdx.z;
    int qc = blockIdx.y;
    int k = (blockIdx.x << 8) + threadIdx.x;
    int nk = g_nk[b];
    if (k >= nk) return;
    int nq = g_nq[b];
    int q0 = qc << 7;
    if (q0 >= nq) { g_vispart[(((long)b * 32 + qc) << 12) + k] = 0.f; return; }
    int q1 = q0 + 128;
    if (q1 > nq) q1 = nq;
    const float* base = att + (long)b * NN * NN + k;
    float s = 0.f;
    for (int q = q0; q < q1; q++) s += base[(long)q << 12];
    g_vispart[(((long)b * 32 + qc) << 12) + k] = s;
}

// ---------------- visatt stage2: sum 32 partials, scatter ------------------
__global__ void k_visatt2() {
    int b = blockIdx.y;
    int k = blockIdx.x * 256 + threadIdx.x;
    int nk = g_nk[b];
    if (k >= nk) return;
    const float* part = g_vispart + (((long)b * 32) << 12) + k;
    float s = 0.f;
#pragma unroll
    for (int qc = 0; qc < 32; qc++) s += part[(long)qc << 12];
    g_vis[(b << 12) + g_kidx[(b << 12) + k]] = s;
}

// ---------------- AV GEMM: converts fp32 V and att inline (R14 exact) -----
__global__ __launch_bounds__(256) void k_av_tc(const float* __restrict__ Vc,
                                               const float* __restrict__ att,
                                               float* __restrict__ out) {
    int b = blockIdx.z;
    int m0 = blockIdx.y << 7;
    int n0 = blockIdx.x << 7;
    if (n0 >= PAD128(g_nq[b])) return;
    int nkp = PAD128(g_nk[b]);
    __shared__ uint32_t sVh[128 * 9], sVl[128 * 9];
    __shared__ uint32_t sPh[8 * 136], sPl[8 * 136];
    int tid = threadIdx.x;
    int w = tid >> 5, l = tid & 31;
    int wm = w & 3, wn = w >> 2;
    int grp = l >> 2, tig = l & 3;
    int r8 = tid >> 3, c8 = tid & 7;

    float acc[2][8][4];
#pragma unroll
    for (int i = 0; i < 2; i++)
#pragma unroll
        for (int j = 0; j < 8; j++)
#pragma unroll
            for (int k = 0; k < 4; k++) acc[i][j][k] = 0.f;

    const float* Vb = Vc + (long)b * CC * NN;
    const float* Pb = att + (long)b * NN * NN;

    for (int jc = 0; jc < nkp; jc += 16) {
#pragma unroll
        for (int it = 0; it < 4; it++) {
            int rr = r8 + (it << 5);
            float2 v = *(const float2*)(Vb + (long)(m0 + rr) * NN + jc + (c8 << 1));
            sVh[rr * 9 + c8] = pack2bf(v.x, v.y);
            sVl[rr * 9 + c8] = pack2bf_lo(v.x, v.y);
            float2 p = *(const float2*)(Pb + (long)(n0 + rr) * NN + jc + (c8 << 1));
            sPh[c8 * 136 + rr] = pack2bf(p.x, p.y);
            sPl[c8 * 136 + rr] = pack2bf_lo(p.x, p.y);
        }
        __syncthreads();
        uint32_t ah[2][4], al[2][4];
#pragma unroll
        for (int mf = 0; mf < 2; mf++) {
            int ab = ((wm << 5) + (mf << 4) + grp) * 9;
            ah[mf][0] = sVh[ab + tig];
            ah[mf][1] = sVh[ab + 72 + tig];
            ah[mf][2] = sVh[ab + tig + 4];
            ah[mf][3] = sVh[ab + 72 + tig + 4];
            al[mf][0] = sVl[ab + tig];
            al[mf][1] = sVl[ab + 72 + tig];
            al[mf][2] = sVl[ab + tig + 4];
            al[mf][3] = sVl[ab + 72 + tig + 4];
        }
#pragma unroll
        for (int nf = 0; nf < 8; nf++) {
            int n = (wn << 6) + (nf << 3) + grp;
            uint32_t bh0 = sPh[tig * 136 + n];
            uint32_t bh1 = sPh[(tig + 4) * 136 + n];
            uint32_t bl0 = sPl[tig * 136 + n];
            uint32_t bl1 = sPl[(tig + 4) * 136 + n];
#pragma unroll
            for (int mf = 0; mf < 2; mf++) {
                mma_bf16(acc[mf][nf], ah[mf], bh0, bh1);
                mma_bf16(acc[mf][nf], ah[mf], bl0, bl1);
                mma_bf16(acc[mf][nf], al[mf], bh0, bh1);
            }
        }
        __syncthreads();
    }
    float* ob = out + (long)b * CC * NN;
#pragma unroll
    for (int mf = 0; mf < 2; mf++) {
        int r0 = m0 + (wm << 5) + (mf << 4) + grp;
#pragma unroll
        for (int nf = 0; nf < 8; nf++) {
            int cc = n0 + (wn << 6) + (nf << 3) + (tig << 1);
            *(float2*)&ob[((long)r0 << 12) + cc] =
                make_float2(acc[mf][nf][0], acc[mf][nf][1]);
            *(float2*)&ob[((long)(r0 + 8) << 12) + cc] =
                make_float2(acc[mf][nf][2], acc[mf][nf][3]);
        }
    }
}

// ---------------- pack att_fore along c (vectorized) -----------------------
// grid 1024 blocks x 256: each thread packs 4 pixels of one cp row
__global__ void k_packF(const float* __restrict__ af) {
    int idx = blockIdx.x * 256 + threadIdx.x;    // < BB*128*1024
    int b = idx >> 17;
    int rem = idx & 131071;
    int cp = rem >> 10, i4 = (rem & 1023) << 2;
    const float* base = af + (long)b * CC * NN;
    float4 v0 = *(const float4*)(base + ((long)(2 * cp) << 12) + i4);
    float4 v1 = *(const float4*)(base + ((long)(2 * cp + 1) << 12) + i4);
    uint4 hq, lq;
    hq.x = pack2bf(v0.x, v1.x);     lq.x = pack2bf_lo(v0.x, v1.x);
    hq.y = pack2bf(v0.y, v1.y);     lq.y = pack2bf_lo(v0.y, v1.y);
    hq.z = pack2bf(v0.z, v1.z);     lq.z = pack2bf_lo(v0.z, v1.z);
    hq.w = pack2bf(v0.w, v1.w);     lq.w = pack2bf_lo(v0.w, v1.w);
    long o = ((long)b << 19) + ((long)cp << 12) + i4;
    *(uint4*)&g_AFph[o] = hq;
    *(uint4*)&g_AFpl[o] = lq;
}

// ---------------- fuse GEMM tensor cores: K=512, scatter out --------------
__global__ __launch_bounds__(256) void k_fuse_tc(float* __restrict__ out) {
    int b = blockIdx.z;
    int m0 = blockIdx.y << 7;
    int n0 = blockIdx.x << 7;
    int nq = g_nq[b];
    if (n0 >= PAD128(nq)) return;
    __shared__ uint32_t sWh[128 * 9], sWl[128 * 9];
    __shared__ uint32_t sFh[8 * 136], sFl[8 * 136];
    int tid = threadIdx.x;
    int w = tid >> 5, l = tid & 31;
    int wm = w & 3, wn = w >> 2;
    int grp = l >> 2, tig = l & 3;
    int q = tid & 127, half = tid >> 7;
    long fbase = ((long)b << 19);

    float acc[2][8][4];
#pragma unroll
    for (int i = 0; i < 2; i++)
#pragma unroll
        for (int j = 0; j < 8; j++)
#pragma unroll
            for (int k = 0; k < 4; k++) acc[i][j][k] = 0.f;

    for (int step = 0; step < 32; step++) {
        int c0p = step << 3;
#pragma unroll
        for (int it = 0; it < 4; it++) {
            int cp = (it << 1) + half;
            int cpg = c0p + cp;
            sWh[q * 9 + cp] = g_WFh[cpg * 256 + m0 + q];
            sWl[q * 9 + cp] = g_WFl[cpg * 256 + m0 + q];
            const uint32_t* Fh = (cpg < 128) ? g_AFph : g_Xqph;
            const uint32_t* Fl = (cpg < 128) ? g_AFpl : g_Xqpl;
            long g = fbase + ((long)(cpg & 127) << 12);
            sFh[cp * 136 + q] = Fh[g + n0 + q];
            sFl[cp * 136 + q] = Fl[g + n0 + q];
        }
        __syncthreads();
        uint32_t ah[2][4], al[2][4];
#pragma unroll
        for (int mf = 0; mf < 2; mf++) {
            int ab = ((wm << 5) + (mf << 4) + grp) * 9;
            ah[mf][0] = sWh[ab + tig];
            ah[mf][1] = sWh[ab + 72 + tig];
            ah[mf][2] = sWh[ab + tig + 4];
            ah[mf][3] = sWh[ab + 72 + tig + 4];
            al[mf][0] = sWl[ab + tig];
            al[mf][1] = sWl[ab + 72 + tig];
            al[mf][2] = sWl[ab + tig + 4];
            al[mf][3] = sWl[ab + 72 + tig + 4];
        }
#pragma unroll
        for (int nf = 0; nf < 8; nf++) {
            int n = (wn << 6) + (nf << 3) + grp;
            uint32_t bh0 = sFh[tig * 136 + n];
            uint32_t bh1 = sFh[(tig + 4) * 136 + n];
            uint32_t bl0 = sFl[tig * 136 + n];
            uint32_t bl1 = sFl[(tig + 4) * 136 + n];
#pragma unroll
            for (int mf = 0; mf < 2; mf++) {
                mma_bf16(acc[mf][nf], ah[mf], bh0, bh1);
                mma_bf16(acc[mf][nf], ah[mf], bl0, bl1);
                mma_bf16(acc[mf][nf], al[mf], bh0, bh1);
            }
        }
        __syncthreads();
    }
    const int* qidx = g_qidx + (b << 12);
#pragma unroll
    for (int mf = 0; mf < 2; mf++) {
        int r0 = m0 + (wm << 5) + (mf << 4) + grp;
#pragma unroll
        for (int nf = 0; nf < 8; nf++) {
            int cc = n0 + (wn << 6) + (nf << 3) + (tig << 1);
            if (cc < nq) {
                int px = qidx[cc];
                out[((b * CC + r0) << 12) + px] = acc[mf][nf][0];
                out[((b * CC + r0 + 8) << 12) + px] = acc[mf][nf][2];
            }
            if (cc + 1 < nq) {
                int px = qidx[cc + 1];
                out[((b * CC + r0) << 12) + px] = acc[mf][nf][1];
                out[((b * CC + r0 + 8) << 12) + px] = acc[mf][nf][3];
            }
        }
    }
}

// ---------------- global max of visatt ----------------------------------
__global__ void k_vismax() {
    float mx = -1e30f;
    for (int i = threadIdx.x; i < BB * NN; i += 256) mx = fmaxf(mx, g_vis[i]);
    mx = warpMax(mx);
    __shared__ float sh[8];
    if ((threadIdx.x & 31) == 0) sh[threadIdx.x >> 5] = mx;
    __syncthreads();
    if (threadIdx.x == 0) {
        float m2 = sh[0];
#pragma unroll
        for (int i = 1; i < 8; i++) m2 = fmaxf(m2, sh[i]);
        g_maxv[0] = m2;
    }
}

// ---------------- attmask --------------------------------------------------
__global__ void k_attmask(float* __restrict__ o) {
    int i = blockIdx.x * 256 + threadIdx.x;
    int b = i >> 18;
    int r = i & 262143;
    int Y = r >> 9, X = r & 511;
    o[i] = g_vis[(b << 12) + ((Y >> 3) << 6) + (X >> 3)] / g_maxv[0];
}

// ---------------- launch -------------------------------------------------
extern "C" void kernel_launch(void* const* d_in, const int* in_sizes, int n_in,
                              void* d_out, int out_size) {
    const float* x = nullptr;
    const float* mask = nullptr;
    const float* w1 = nullptr;
    const float* w2 = nullptr;
    const float* wf = nullptr;
    int seen589 = 0;
    for (int i = 0; i < n_in; i++) {
        switch (in_sizes[i]) {
            case 2097152: x = (const float*)d_in[i]; break;
            case 524288:  mask = (const float*)d_in[i]; break;
            case 589824:
                if (seen589++ == 0) w1 = (const float*)d_in[i];
                else w2 = (const float*)d_in[i];
                break;
            case 131072:  wf = (const float*)d_in[i]; break;
            default: break;
        }
    }

    float *bufA, *bufB, *Vc, *att;
    __nv_bfloat16 *xh, *xl, *f1h, *f1l;
    uint32_t *w1h, *w1l, *w2h, *w2l;
    cudaGetSymbolAddress((void**)&bufA, g_bufA);
    cudaGetSymbolAddress((void**)&bufB, g_bufB);
    cudaGetSymbolAddress((void**)&Vc, g_Vc);
    cudaGetSymbolAddress((void**)&att, g_att);
    cudaGetSymbolAddress((void**)&xh, g_xh);
    cudaGetSymbolAddress((void**)&xl, g_xl);
    cudaGetSymbolAddress((void**)&f1h, g_f1h);
    cudaGetSymbolAddress((void**)&f1l, g_f1l);
    cudaGetSymbolAddress((void**)&w1h, g_w1h);
    cudaGetSymbolAddress((void**)&w1l, g_w1l);
    cudaGetSymbolAddress((void**)&w2h, g_w2h);
    cudaGetSymbolAddress((void**)&w2l, g_w2l);

    static cudaStream_t s1 = nullptr;
    static cudaEvent_t ev0 = nullptr, ev1 = nullptr, ev2 = nullptr, ev3 = nullptr;
    static int smem_set = 0;
    const int CONV_SMEM = (13824 + 9216 + 1728 * 2) * 4;   // 105984 B
    if (!smem_set) {
        cudaFuncSetAttribute(k_conv_tc, cudaFuncAttributeMaxDynamicSharedMemorySize,
                             CONV_SMEM);
        cudaStreamCreateWithFlags(&s1, cudaStreamNonBlocking);
        cudaEventCreateWithFlags(&ev0, cudaEventDisableTiming);
        cudaEventCreateWithFlags(&ev1, cudaEventDisableTiming);
        cudaEventCreateWithFlags(&ev2, cudaEventDisableTiming);
        cudaEventCreateWithFlags(&ev3, cudaEventDisableTiming);
        smem_set = 1;
    }

    float* out = (float*)d_out;
    float* attm = out + (long)BB * CC * NN;

    // fork: side stream does memcpy + weight/input packing
    cudaEventRecord(ev0, 0);
    cudaStreamWaitEvent(s1, ev0, 0);
    cudaMemcpyAsync(out, x, (size_t)BB * CC * NN * sizeof(float),
                    cudaMemcpyDeviceToDevice, s1);
    k_packW<<<1152, 256, 0, s1>>>(w1, w1h, w1l);
    k_packW<<<1152, 256, 0, s1>>>(w2, w2h, w2l);
    k_packWF<<<256, 256, 0, s1>>>(wf);
    k_packX<<<8192, 256, 0, s1>>>(x, xh, xl);
    cudaEventRecord(ev1, s1);

    // main stream: mask/compact concurrently with the packing above
    k_mask<<<32, 256>>>(mask);
    k_compact<<<BB, 256>>>();
    cudaStreamWaitEvent(0, ev1, 0);

    k_conv_tc<<<dim3(64, 2, BB), 256, CONV_SMEM>>>(xh, xl, w1h, w1l, bufA);
    k_inorm0<<<BB * CC, 256>>>(bufA, f1h, f1l);
    k_conv_tc<<<dim3(64, 2, BB), 256, CONV_SMEM>>>(f1h, f1l, w2h, w2l, bufA);
    k_inorm1<<<BB * CC, 256>>>(bufA, x, bufB);            // bufB = feat
    k_rn<<<32, 256>>>(bufB);
    k_gather<<<dim3(16, 2, BB), 256>>>(bufB, x);          // Qp, Kp, Xqp, Vc
    k_score_tc<<<dim3(32, 32, BB), 256>>>(att);
    k_softmax<<<dim3(4096, BB), 256>>>(att);              // in-place fp32

    // fork: visatt chain + attmask on side stream, concurrent with av/fuse
    cudaEventRecord(ev2, 0);
    cudaStreamWaitEvent(s1, ev2, 0);
    k_visatt1<<<dim3(8, 32, BB), 256, 0, s1>>>(att);
    k_visatt2<<<dim3(8, BB), 256, 0, s1>>>();
    k_vismax<<<1, 256, 0, s1>>>();
    k_attmask<<<2048, 256, 0, s1>>>(attm);
    cudaEventRecord(ev3, s1);

    k_av_tc<<<dim3(32, 2, BB), 256>>>(Vc, att, bufA);     // bufA = att_fore
    k_packF<<<1024, 256>>>(bufA);
    k_fuse_tc<<<dim3(32, 2, BB), 256>>>(out);

    // join: attmask must complete before capture ends
    cudaStreamWaitEvent(0, ev3, 0);
}

// round 17
// speedup vs baseline: 1.0141x; 1.0001x over previous
#include <cuda_runtime.h>
#include <cuda_bf16.h>
#include <math.h>
#include <stdint.h>

#define BB 2
#define CC 256
#define NN 4096
#define EPS_IN 1e-5f
#define EPS_NORM 1e-8f
#define SCALE 20.0f
#define PAD128(v) (((v) + 127) & ~127)

// ---------------- static scratch ----------------
__device__ float g_m[BB * NN];
__device__ int   g_qidx[BB * NN];
__device__ int   g_kidx[BB * NN];
__device__ int   g_nq[BB];
__device__ int   g_nk[BB];
__device__ float g_bufA[BB * CC * NN];   // conv out fp32 / att_fore
__device__ float g_bufB[BB * CC * NN];   // feat
__device__ float g_Vc[BB * CC * NN];
__device__ float g_att[(long)BB * NN * NN];   // scores -> att in place (fp32)
__device__ float g_vis[BB * NN];
__device__ float g_vispart[BB * 32 * NN];
__device__ float g_maxv[1];

// bf16 split inputs for tensor-core convs
__device__ __nv_bfloat16 g_xh[BB * CC * NN];
__device__ __nv_bfloat16 g_xl[BB * CC * NN];
__device__ __nv_bfloat16 g_f1h[BB * CC * NN];
__device__ __nv_bfloat16 g_f1l[BB * CC * NN];
// packed conv weights: [chunk 16][kap 9][co 256][cipair-in-chunk 8] u32
#define WPK (16 * 9 * 256 * 8)
__device__ uint32_t g_w1h[WPK];
__device__ uint32_t g_w1l[WPK];
__device__ uint32_t g_w2h[WPK];
__device__ uint32_t g_w2l[WPK];

// packed Q/K/Xq: [b][cp 128][i 4096] u32 (pair along c)
__device__ uint32_t g_Qph[BB * 128 * NN];
__device__ uint32_t g_Qpl[BB * 128 * NN];
__device__ uint32_t g_Kph[BB * 128 * NN];
__device__ uint32_t g_Kpl[BB * 128 * NN];
__device__ uint32_t g_Xqph[BB * 128 * NN];
__device__ uint32_t g_Xqpl[BB * 128 * NN];
// packed AF (att_fore): [b][cp 128][i 4096]
__device__ uint32_t g_AFph[BB * 128 * NN];
__device__ uint32_t g_AFpl[BB * 128 * NN];
// packed fuse weights: [cp 256][co 256]
__device__ uint32_t g_WFh[256 * 256];
__device__ uint32_t g_WFl[256 * 256];

__device__ __forceinline__ float warpMax(float v) {
#pragma unroll
    for (int o = 16; o; o >>= 1) v = fmaxf(v, __shfl_xor_sync(0xffffffffu, v, o));
    return v;
}
__device__ __forceinline__ float warpSum(float v) {
#pragma unroll
    for (int o = 16; o; o >>= 1) v += __shfl_xor_sync(0xffffffffu, v, o);
    return v;
}

__device__ __forceinline__ void mma_bf16(float c[4], const uint32_t a[4],
                                         uint32_t b0, uint32_t b1) {
    asm volatile(
        "mma.sync.aligned.m16n8k16.row.col.f32.bf16.bf16.f32 "
        "{%0,%1,%2,%3}, {%4,%5,%6,%7}, {%8,%9}, {%0,%1,%2,%3};"
        : "+f"(c[0]), "+f"(c[1]), "+f"(c[2]), "+f"(c[3])
        : "r"(a[0]), "r"(a[1]), "r"(a[2]), "r"(a[3]), "r"(b0), "r"(b1));
}

__device__ __forceinline__ uint32_t pack2bf(float v0, float v1) {
    __nv_bfloat16 h0 = __float2bfloat16(v0);
    __nv_bfloat16 h1 = __float2bfloat16(v1);
    return (uint32_t)__bfloat16_as_ushort(h0) |
           ((uint32_t)__bfloat16_as_ushort(h1) << 16);
}
__device__ __forceinline__ uint32_t pack2bf_lo(float v0, float v1) {
    float h0 = __bfloat162float(__float2bfloat16(v0));
    float h1 = __bfloat162float(__float2bfloat16(v1));
    return pack2bf(v0 - h0, v1 - h1);
}

// ---------------- mask: MaxPool2d(8,8) > 0; also zero g_vis ---------------
__global__ void k_mask(const float* __restrict__ mask) {
    int gid = blockIdx.x * 256 + threadIdx.x;
    int b = gid >> 12;
    int j = gid & 4095;
    int py = j >> 6, px = j & 63;
    const float* mp = mask + (long)b * 262144 + (py * 8) * 512 + px * 8;
    float mx = 0.f;
#pragma unroll
    for (int dy = 0; dy < 8; dy++)
#pragma unroll
        for (int dx = 0; dx < 8; dx++) mx = fmaxf(mx, mp[dy * 512 + dx]);
    g_m[gid] = (mx > 0.f) ? 1.f : 0.f;
    g_vis[gid] = 0.f;
}

// ---------------- deterministic compaction --------------------------------
__global__ __launch_bounds__(256) void k_compact() {
    int b = blockIdx.x;
    int tid = threadIdx.x;
    __shared__ int wsum[8];
    __shared__ int baseq, basek;
    if (tid == 0) { baseq = 0; basek = 0; }
    __syncthreads();
    for (int chunk = 0; chunk < 16; chunk++) {
        int px = (chunk << 8) + tid;
        int vq = (g_m[(b << 12) + px] > 0.5f) ? 1 : 0;
        unsigned bal = __ballot_sync(0xffffffffu, vq);
        int lane = tid & 31, w = tid >> 5;
        int pre = __popc(bal & ((1u << lane) - 1u));
        if (lane == 0) wsum[w] = __popc(bal);
        __syncthreads();
        int woff = 0, tot = 0;
#pragma unroll
        for (int i = 0; i < 8; i++) {
            if (i < w) woff += wsum[i];
            tot += wsum[i];
        }
        int bq = baseq, bk = basek;
        int qbefore = woff + pre;
        if (vq) g_qidx[(b << 12) + bq + qbefore] = px;
        else    g_kidx[(b << 12) + bk + (tid - qbefore)] = px;
        __syncthreads();
        if (tid == 0) { baseq = bq + tot; basek = bk + (256 - tot); }
        __syncthreads();
    }
    if (tid == 0) { g_nq[b] = baseq; g_nk[b] = basek; }
}

// ---------------- pack conv weights ----------------------------------------
__global__ void k_packW(const float* __restrict__ w,
                        uint32_t* __restrict__ oh, uint32_t* __restrict__ ol) {
    int idx = blockIdx.x * 256 + threadIdx.x;   // < 294912
    int cpw = idx & 7;
    int co = (idx >> 3) & 255;
    int t = idx >> 11;
    int chunk = t / 9;
    int kap = t - chunk * 9;
    int cp = (chunk << 3) + cpw;
    float v0 = w[(co * 256 + 2 * cp) * 9 + kap];
    float v1 = w[(co * 256 + 2 * cp + 1) * 9 + kap];
    oh[idx] = pack2bf(v0, v1);
    ol[idx] = pack2bf_lo(v0, v1);
}

// ---------------- pack fuse weights: wf[co][512] -> [cp 256][co 256] -------
__global__ void k_packWF(const float* __restrict__ wf) {
    int idx = blockIdx.x * 256 + threadIdx.x;   // < 65536
    int cp = idx >> 8, co = idx & 255;
    float v0 = wf[co * 512 + 2 * cp];
    float v1 = wf[co * 512 + 2 * cp + 1];
    g_WFh[cp * 256 + co] = pack2bf(v0, v1);
    g_WFl[cp * 256 + co] = pack2bf_lo(v0, v1);
}

// ---------------- split x -> bf16 hi/lo ------------------------------------
__global__ void k_packX(const float* __restrict__ x,
                        __nv_bfloat16* __restrict__ xh,
                        __nv_bfloat16* __restrict__ xl) {
    int i = blockIdx.x * 256 + threadIdx.x;
    float v = x[i];
    __nv_bfloat16 h = __float2bfloat16(v);
    xh[i] = h;
    xl[i] = __float2bfloat16(v - __bfloat162float(h));
}

// ---------------- tensor-core conv3x3: implicit GEMM (R12 exact) ----------
__global__ __launch_bounds__(256) void k_conv_tc(const __nv_bfloat16* __restrict__ xh,
                                                 const __nv_bfloat16* __restrict__ xl,
                                                 const uint32_t* __restrict__ wph,
                                                 const uint32_t* __restrict__ wpl,
                                                 float* __restrict__ out) {
    extern __shared__ uint32_t dsm[];
    uint32_t* sAh = dsm;                 // 9*128*12 = 13824
    uint32_t* sAl = sAh + 13824;         // 9*128*8  = 9216
    uint32_t* sBh = sAl + 9216;          // 24 rows * 72
    uint32_t* sBl = sBh + 1728;

    int tid = threadIdx.x;
    int ytile = blockIdx.x;
    int co0 = blockIdx.y << 7;
    int b = blockIdx.z;
    int w = tid >> 5, l = tid & 31;
    int wm = w & 3, wn = w >> 2;
    int grp = l >> 2, tig = l & 3;

    float acc[2][4][4];
#pragma unroll
    for (int i = 0; i < 2; i++)
#pragma unroll
        for (int j = 0; j < 4; j++)
#pragma unroll
            for (int k = 0; k < 4; k++) acc[i][j][k] = 0.f;

    long xbase = (long)b * CC * NN;

    for (int chunk = 0; chunk < 16; chunk++) {
        int ci0 = chunk << 4;
        if (tid < 192) {
            int srow = tid >> 6;
            int rem = tid & 63;
            int pair = rem >> 3, cg = rem & 7;
            int gy = ytile - 1 + srow;
            int sb = (srow * 8 + pair) * 72 + 4 + (cg << 3);
            if ((unsigned)gy < 64u) {
                long e = xbase + (long)(ci0 + (pair << 1)) * NN + (gy << 6) + (cg << 3);
                long o = e + NN;
                uint4 ev = *(const uint4*)(xh + e);
                uint4 od = *(const uint4*)(xh + o);
                uint4 r0, r1;
                r0.x = __byte_perm(ev.x, od.x, 0x5410);
                r0.y = __byte_perm(ev.x, od.x, 0x7632);
                r0.z = __byte_perm(ev.y, od.y, 0x5410);
                r0.w = __byte_perm(ev.y, od.y, 0x7632);
                r1.x = __byte_perm(ev.z, od.z, 0x5410);
                r1.y = __byte_perm(ev.z, od.z, 0x7632);
                r1.z = __byte_perm(ev.w, od.w, 0x5410);
                r1.w = __byte_perm(ev.w, od.w, 0x7632);
                *(uint4*)&sBh[sb] = r0;
                *(uint4*)&sBh[sb + 4] = r1;
                ev = *(const uint4*)(xl + e);
                od = *(const uint4*)(xl + o);
                r0.x = __byte_perm(ev.x, od.x, 0x5410);
                r0.y = __byte_perm(ev.x, od.x, 0x7632);
                r0.z = __byte_perm(ev.y, od.y, 0x5410);
                r0.w = __byte_perm(ev.y, od.y, 0x7632);
                r1.x = __byte_perm(ev.z, od.z, 0x5410);
                r1.y = __byte_perm(ev.z, od.z, 0x7632);
                r1.z = __byte_perm(ev.w, od.w, 0x5410);
                r1.w = __byte_perm(ev.w, od.w, 0x7632);
                *(uint4*)&sBl[sb] = r0;
                *(uint4*)&sBl[sb + 4] = r1;
            } else {
                uint4 z = make_uint4(0, 0, 0, 0);
                *(uint4*)&sBh[sb] = z;
                *(uint4*)&sBh[sb + 4] = z;
                *(uint4*)&sBl[sb] = z;
                *(uint4*)&sBl[sb + 4] = z;
            }
        }
        if (tid >= 192 && tid < 240) {
            int t2 = tid - 192;
            int srow = t2 / 16, rem = t2 % 16;
            int pair = rem >> 1, edge = rem & 1;
            int off = (srow * 8 + pair) * 72 + (edge ? 68 : 3);
            sBh[off] = 0;
            sBl[off] = 0;
        }
        {
            long wb = (long)chunk * 9 * 2048;
            for (int idx = tid; idx < 2304; idx += 256) {
                int kap = idx >> 8;
                int rem = idx & 255;
                int row = rem >> 1, colh = (rem & 1) << 2;
                long g = wb + (long)kap * 2048 + ((long)(co0 + row) << 3) + colh;
                *(uint4*)&sAh[kap * 1536 + row * 12 + colh] =
                    *(const uint4*)(wph + g);
                *(uint4*)&sAl[kap * 1024 + (row << 3) + colh] =
                    *(const uint4*)(wpl + g);
            }
        }
        __syncthreads();

#pragma unroll
        for (int kap = 0; kap < 9; kap++) {
            int dy = kap / 3, dx = kap - dy * 3;
            uint32_t ah[2][4], al[2][4];
#pragma unroll
            for (int mf = 0; mf < 2; mf++) {
                int mr = (wm << 5) + (mf << 4);
                int abh = kap * 1536 + (mr + grp) * 12;
                int abl = kap * 1024 + ((mr + grp) << 3);
                ah[mf][0] = sAh[abh + tig];
                ah[mf][1] = sAh[abh + 96 + tig];
                ah[mf][2] = sAh[abh + tig + 4];
                ah[mf][3] = sAh[abh + 96 + tig + 4];
                al[mf][0] = sAl[abl + tig];
                al[mf][1] = sAl[abl + 64 + tig];
                al[mf][2] = sAl[abl + tig + 4];
                al[mf][3] = sAl[abl + 64 + tig + 4];
            }
#pragma unroll
            for (int nf = 0; nf < 4; nf++) {
                int n = (wn << 5) + (nf << 3) + grp;
                int a0 = (dy * 8 + tig) * 72 + n + dx + 3;
                uint32_t bh0 = sBh[a0];
                uint32_t bh1 = sBh[a0 + 288];
                uint32_t bl0 = sBl[a0];
                uint32_t bl1 = sBl[a0 + 288];
#pragma unroll
                for (int mf = 0; mf < 2; mf++) {
                    mma_bf16(acc[mf][nf], ah[mf], bh0, bh1);
                    mma_bf16(acc[mf][nf], ah[mf], bl0, bl1);
                    mma_bf16(acc[mf][nf], al[mf], bh0, bh1);
                }
            }
        }
        __syncthreads();
    }
#pragma unroll
    for (int mf = 0; mf < 2; mf++) {
        int r0 = co0 + (wm << 5) + (mf << 4) + grp;
#pragma unroll
        for (int nf = 0; nf < 4; nf++) {
            int p = (ytile << 6) + (wn << 5) + (nf << 3) + (tig << 1);
            *(float2*)&out[((long)(b * CC + r0) << 12) + p] =
                make_float2(acc[mf][nf][0], acc[mf][nf][1]);
            *(float2*)&out[((long)(b * CC + r0 + 8) << 12) + p] =
                make_float2(acc[mf][nf][2], acc[mf][nf][3]);
        }
    }
}

// ---------------- instance norm + relu -> bf16 split ----------------------
__global__ __launch_bounds__(256) void k_inorm0(const float* __restrict__ t,
                                                __nv_bfloat16* __restrict__ oh,
                                                __nv_bfloat16* __restrict__ ol) {
    long base = (long)blockIdx.x * NN;
    int tid = threadIdx.x;
    float s = 0.f, s2 = 0.f;
    for (int i = tid; i < NN; i += 256) {
        float v = t[base + i];
        s += v;
        s2 = fmaf(v, v, s2);
    }
    __shared__ float sh[16];
    __shared__ float smu, srs;
    s = warpSum(s);
    s2 = warpSum(s2);
    int wi = tid >> 5, l = tid & 31;
    if (l == 0) { sh[wi] = s; sh[8 + wi] = s2; }
    __syncthreads();
    if (tid == 0) {
        float a = 0.f, b2 = 0.f;
#pragma unroll
        for (int i = 0; i < 8; i++) { a += sh[i]; b2 += sh[8 + i]; }
        float mu = a * (1.f / NN);
        float var = b2 * (1.f / NN) - mu * mu;
        smu = mu;
        srs = rsqrtf(var + EPS_IN);
    }
    __syncthreads();
    float mu = smu, rs = srs;
    for (int i = tid; i < NN; i += 256) {
        float v = fmaxf((t[base + i] - mu) * rs, 0.f);
        __nv_bfloat16 h = __float2bfloat16(v);
        oh[base + i] = h;
        ol[base + i] = __float2bfloat16(v - __bfloat162float(h));
    }
}

// ---------------- instance norm + residual + relu -> fp32 -----------------
__global__ __launch_bounds__(256) void k_inorm1(const float* __restrict__ t,
                                                const float* __restrict__ xadd,
                                                float* __restrict__ o) {
    long base = (long)blockIdx.x * NN;
    int tid = threadIdx.x;
    float s = 0.f, s2 = 0.f;
    for (int i = tid; i < NN; i += 256) {
        float v = t[base + i];
        s += v;
        s2 = fmaf(v, v, s2);
    }
    __shared__ float sh[16];
    __shared__ float smu, srs;
    s = warpSum(s);
    s2 = warpSum(s2);
    int wi = tid >> 5, l = tid & 31;
    if (l == 0) { sh[wi] = s; sh[8 + wi] = s2; }
    __syncthreads();
    if (tid == 0) {
        float a = 0.f, b2 = 0.f;
#pragma unroll
        for (int i = 0; i < 8; i++) { a += sh[i]; b2 += sh[8 + i]; }
        float mu = a * (1.f / NN);
        float var = b2 * (1.f / NN) - mu * mu;
        smu = mu;
        srs = rsqrtf(var + EPS_IN);
    }
    __syncthreads();
    float mu = smu, rs = srs;
    for (int i = tid; i < NN; i += 256)
        o[base + i] = fmaxf((t[base + i] - mu) * rs + xadd[base + i], 0.f);
}

// ---------------- gather (fused rn): packed Q/K (+Xq), fp32 Vc ------------
__global__ __launch_bounds__(256) void k_gather(const float* __restrict__ feat,
                                                const float* __restrict__ x) {
    int b = blockIdx.z;
    int side = blockIdx.y;
    int i = (blockIdx.x << 8) + threadIdx.x;
    int n = side ? g_nk[b] : g_nq[b];
    int npad = PAD128(n);
    if (i >= npad) return;
    uint32_t* Ph = side ? g_Kph : g_Qph;
    uint32_t* Pl = side ? g_Kpl : g_Qpl;
    long off = (long)b * CC * NN;
    long poff = ((long)b << 19);
    if (i < n) {
        int px = side ? g_kidx[(b << 12) + i] : g_qidx[(b << 12) + i];
        const float* fb = feat + off + px;
        const float* xb = x + off + px;
        // pass 1: channel L2 norm (coalesced; warms L2 for pass 2)
        float ssq = 0.f;
        for (int c = 0; c < CC; c++) {
            float f = fb[c << 12];
            ssq = fmaf(f, f, ssq);
        }
        float rn = 1.f / (sqrtf(ssq) + EPS_NORM);
        // pass 2: pack (L2 hits)
        for (int c = 0; c < CC; c += 2) {
            float v0 = fb[c << 12] * rn;
            float v1 = fb[(c + 1) << 12] * rn;
            long pi = poff + ((long)(c >> 1) << 12) + i;
            Ph[pi] = pack2bf(v0, v1);
            Pl[pi] = pack2bf_lo(v0, v1);
            if (side) {
                g_Vc[off + (c << 12) + i] = xb[c << 12];
                g_Vc[off + ((c + 1) << 12) + i] = xb[(c + 1) << 12];
            } else {
                float u0 = xb[c << 12];
                float u1 = xb[(c + 1) << 12];
                g_Xqph[pi] = pack2bf(u0, u1);
                g_Xqpl[pi] = pack2bf_lo(u0, u1);
            }
        }
    } else {
        for (int c = 0; c < CC; c += 2) {
            long pi = poff + ((long)(c >> 1) << 12) + i;
            Ph[pi] = 0; Pl[pi] = 0;
            if (side) {
                g_Vc[off + (c << 12) + i] = 0.f;
                g_Vc[off + ((c + 1) << 12) + i] = 0.f;
            } else {
                g_Xqph[pi] = 0; g_Xqpl[pi] = 0;
            }
        }
    }
}

// ---------------- score GEMM tensor cores: 128q x 128k --------------------
__global__ __launch_bounds__(256) void k_score_tc(float* __restrict__ att) {
    int b = blockIdx.z;
    int q0 = blockIdx.y << 7;
    int k0 = blockIdx.x << 7;
    if (q0 >= PAD128(g_nq[b]) || k0 >= PAD128(g_nk[b])) return;
    __shared__ uint32_t sQh[128 * 9], sQl[128 * 9];
    __shared__ uint32_t sKh[8 * 136], sKl[8 * 136];
    int tid = threadIdx.x;
    int w = tid >> 5, l = tid & 31;
    int wm = w & 3, wn = w >> 2;
    int grp = l >> 2, tig = l & 3;
    int q = tid & 127, half = tid >> 7;
    long pbase = ((long)b << 19);

    float acc[2][8][4];
#pragma unroll
    for (int i = 0; i < 2; i++)
#pragma unroll
        for (int j = 0; j < 8; j++)
#pragma unroll
            for (int k = 0; k < 4; k++) acc[i][j][k] = 0.f;

    for (int step = 0; step < 16; step++) {
        int c0p = step << 3;
#pragma unroll
        for (int it = 0; it < 4; it++) {
            int cp = (it << 1) + half;
            long g = pbase + ((long)(c0p + cp) << 12);
            sQh[q * 9 + cp] = g_Qph[g + q0 + q];
            sQl[q * 9 + cp] = g_Qpl[g + q0 + q];
            sKh[cp * 136 + q] = g_Kph[g + k0 + q];
            sKl[cp * 136 + q] = g_Kpl[g + k0 + q];
        }
        __syncthreads();
        uint32_t ah[2][4], al[2][4];
#pragma unroll
        for (int mf = 0; mf < 2; mf++) {
            int ab = ((wm << 5) + (mf << 4) + grp) * 9;
            ah[mf][0] = sQh[ab + tig];
            ah[mf][1] = sQh[ab + 72 + tig];
            ah[mf][2] = sQh[ab + tig + 4];
            ah[mf][3] = sQh[ab + 72 + tig + 4];
            al[mf][0] = sQl[ab + tig];
            al[mf][1] = sQl[ab + 72 + tig];
            al[mf][2] = sQl[ab + tig + 4];
            al[mf][3] = sQl[ab + 72 + tig + 4];
        }
#pragma unroll
        for (int nf = 0; nf < 8; nf++) {
            int n = (wn << 6) + (nf << 3) + grp;
            uint32_t bh0 = sKh[tig * 136 + n];
            uint32_t bh1 = sKh[(tig + 4) * 136 + n];
            uint32_t bl0 = sKl[tig * 136 + n];
            uint32_t bl1 = sKl[(tig + 4) * 136 + n];
#pragma unroll
            for (int mf = 0; mf < 2; mf++) {
                mma_bf16(acc[mf][nf], ah[mf], bh0, bh1);
                mma_bf16(acc[mf][nf], ah[mf], bl0, bl1);
                mma_bf16(acc[mf][nf], al[mf], bh0, bh1);
            }
        }
        __syncthreads();
    }
    float* Cb = att + (long)b * NN * NN;
#pragma unroll
    for (int mf = 0; mf < 2; mf++) {
        int r0 = q0 + (wm << 5) + (mf << 4) + grp;
#pragma unroll
        for (int nf = 0; nf < 8; nf++) {
            int cc = k0 + (wn << 6) + (nf << 3) + (tig << 1);
            *(float2*)&Cb[(long)r0 * NN + cc] =
                make_float2(acc[mf][nf][0] * SCALE, acc[mf][nf][1] * SCALE);
            *(float2*)&Cb[(long)(r0 + 8) * NN + cc] =
                make_float2(acc[mf][nf][2] * SCALE, acc[mf][nf][3] * SCALE);
        }
    }
}

// ---------------- softmax in place (fp32, R4 exact) ------------------------
__global__ __launch_bounds__(256) void k_softmax(float* __restrict__ att) {
    int b = blockIdx.y;
    int i = blockIdx.x;
    int nq = g_nq[b];
    if (i >= nq) return;
    int nk = g_nk[b];
    int nkp = PAD128(nk);
    float* row = att + (long)b * NN * NN + (long)i * NN;
    int tid = threadIdx.x;
    float vals[16];
    float mx = -1e30f;
    int nt = (nkp + 255) >> 8;
#pragma unroll
    for (int t = 0; t < 16; t++) {
        if (t >= nt) break;
        int k = tid + (t << 8);
        float s = (k < nk) ? row[k] : -1e30f;
        vals[t] = s;
        mx = fmaxf(mx, s);
    }
    __shared__ float sh[8];
    __shared__ float bval;
    mx = warpMax(mx);
    int wi = tid >> 5, l = tid & 31;
    if (l == 0) sh[wi] = mx;
    __syncthreads();
    if (tid == 0) {
        float m2 = sh[0];
#pragma unroll
        for (int ii = 1; ii < 8; ii++) m2 = fmaxf(m2, sh[ii]);
        bval = m2;
    }
    __syncthreads();
    mx = bval;
    float sum = 0.f;
#pragma unroll
    for (int t = 0; t < 16; t++) {
        if (t >= nt) break;
        float e = __expf(vals[t] - mx);
        vals[t] = e;
        sum += e;
    }
    sum = warpSum(sum);
    __syncthreads();
    if (l == 0) sh[wi] = sum;
    __syncthreads();
    if (tid == 0) {
        float s2 = 0.f;
#pragma unroll
        for (int ii = 0; ii < 8; ii++) s2 += sh[ii];
        bval = 1.f / s2;
    }
    __syncthreads();
    float rinv = bval;
#pragma unroll
    for (int t = 0; t < 16; t++) {
        if (t >= nt) break;
        int k = tid + (t << 8);
        row[k] = (k < nk) ? vals[t] * rinv : 0.f;
    }
}

// ---------------- visatt stage1: coalesced partial column sums ------------
__global__ __launch_bounds__(256) void k_visatt1(const float* __restrict__ att) {
    int b = blockIdx.z;
    int qc = blockIdx.y;
    int k = (blockIdx.x << 8) + threadIdx.x;
    int nk = g_nk[b];
    if (k >= nk) return;
    int nq = g_nq[b];
    int q0 = qc << 7;
    if (q0 >= nq) { g_vispart[(((long)b * 32 + qc) << 12) + k] = 0.f; return; }
    int q1 = q0 + 128;
    if (q1 > nq) q1 = nq;
    const float* base = att + (long)b * NN * NN + k;
    float s = 0.f;
    for (int q = q0; q < q1; q++) s += base[(long)q << 12];
    g_vispart[(((long)b * 32 + qc) << 12) + k] = s;
}

// ---------------- visatt stage2: sum 32 partials, scatter ------------------
__global__ void k_visatt2() {
    int b = blockIdx.y;
    int k = blockIdx.x * 256 + threadIdx.x;
    int nk = g_nk[b];
    if (k >= nk) return;
    const float* part = g_vispart + (((long)b * 32) << 12) + k;
    float s = 0.f;
#pragma unroll
    for (int qc = 0; qc < 32; qc++) s += part[(long)qc << 12];
    g_vis[(b << 12) + g_kidx[(b << 12) + k]] = s;
}

// ---------------- AV GEMM: converts fp32 V and att inline (R14 exact) -----
__global__ __launch_bounds__(256) void k_av_tc(const float* __restrict__ Vc,
                                               const float* __restrict__ att,
                                               float* __restrict__ out) {
    int b = blockIdx.z;
    int m0 = blockIdx.y << 7;
    int n0 = blockIdx.x << 7;
    if (n0 >= PAD128(g_nq[b])) return;
    int nkp = PAD128(g_nk[b]);
    __shared__ uint32_t sVh[128 * 9], sVl[128 * 9];
    __shared__ uint32_t sPh[8 * 136], sPl[8 * 136];
    int tid = threadIdx.x;
    int w = tid >> 5, l = tid & 31;
    int wm = w & 3, wn = w >> 2;
    int grp = l >> 2, tig = l & 3;
    int r8 = tid >> 3, c8 = tid & 7;

    float acc[2][8][4];
#pragma unroll
    for (int i = 0; i < 2; i++)
#pragma unroll
        for (int j = 0; j < 8; j++)
#pragma unroll
            for (int k = 0; k < 4; k++) acc[i][j][k] = 0.f;

    const float* Vb = Vc + (long)b * CC * NN;
    const float* Pb = att + (long)b * NN * NN;

    for (int jc = 0; jc < nkp; jc += 16) {
#pragma unroll
        for (int it = 0; it < 4; it++) {
            int rr = r8 + (it << 5);
            float2 v = *(const float2*)(Vb + (long)(m0 + rr) * NN + jc + (c8 << 1));
            sVh[rr * 9 + c8] = pack2bf(v.x, v.y);
            sVl[rr * 9 + c8] = pack2bf_lo(v.x, v.y);
            float2 p = *(const float2*)(Pb + (long)(n0 + rr) * NN + jc + (c8 << 1));
            sPh[c8 * 136 + rr] = pack2bf(p.x, p.y);
            sPl[c8 * 136 + rr] = pack2bf_lo(p.x, p.y);
        }
        __syncthreads();
        uint32_t ah[2][4], al[2][4];
#pragma unroll
        for (int mf = 0; mf < 2; mf++) {
            int ab = ((wm << 5) + (mf << 4) + grp) * 9;
            ah[mf][0] = sVh[ab + tig];
            ah[mf][1] = sVh[ab + 72 + tig];
            ah[mf][2] = sVh[ab + tig + 4];
            ah[mf][3] = sVh[ab + 72 + tig + 4];
            al[mf][0] = sVl[ab + tig];
            al[mf][1] = sVl[ab + 72 + tig];
            al[mf][2] = sVl[ab + tig + 4];
            al[mf][3] = sVl[ab + 72 + tig + 4];
        }
#pragma unroll
        for (int nf = 0; nf < 8; nf++) {
            int n = (wn << 6) + (nf << 3) + grp;
            uint32_t bh0 = sPh[tig * 136 + n];
            uint32_t bh1 = sPh[(tig + 4) * 136 + n];
            uint32_t bl0 = sPl[tig * 136 + n];
            uint32_t bl1 = sPl[(tig + 4) * 136 + n];
#pragma unroll
            for (int mf = 0; mf < 2; mf++) {
                mma_bf16(acc[mf][nf], ah[mf], bh0, bh1);
                mma_bf16(acc[mf][nf], ah[mf], bl0, bl1);
                mma_bf16(acc[mf][nf], al[mf], bh0, bh1);
            }
        }
        __syncthreads();
    }
    float* ob = out + (long)b * CC * NN;
#pragma unroll
    for (int mf = 0; mf < 2; mf++) {
        int r0 = m0 + (wm << 5) + (mf << 4) + grp;
#pragma unroll
        for (int nf = 0; nf < 8; nf++) {
            int cc = n0 + (wn << 6) + (nf << 3) + (tig << 1);
            *(float2*)&ob[((long)r0 << 12) + cc] =
                make_float2(acc[mf][nf][0], acc[mf][nf][1]);
            *(float2*)&ob[((long)(r0 + 8) << 12) + cc] =
                make_float2(acc[mf][nf][2], acc[mf][nf][3]);
        }
    }
}

// ---------------- pack att_fore along c (vectorized) -----------------------
__global__ void k_packF(const float* __restrict__ af) {
    int idx = blockIdx.x * 256 + threadIdx.x;    // < BB*128*1024
    int b = idx >> 17;
    int rem = idx & 131071;
    int cp = rem >> 10, i4 = (rem & 1023) << 2;
    const float* base = af + (long)b * CC * NN;
    float4 v0 = *(const float4*)(base + ((long)(2 * cp) << 12) + i4);
    float4 v1 = *(const float4*)(base + ((long)(2 * cp + 1) << 12) + i4);
    uint4 hq, lq;
    hq.x = pack2bf(v0.x, v1.x);     lq.x = pack2bf_lo(v0.x, v1.x);
    hq.y = pack2bf(v0.y, v1.y);     lq.y = pack2bf_lo(v0.y, v1.y);
    hq.z = pack2bf(v0.z, v1.z);     lq.z = pack2bf_lo(v0.z, v1.z);
    hq.w = pack2bf(v0.w, v1.w);     lq.w = pack2bf_lo(v0.w, v1.w);
    long o = ((long)b << 19) + ((long)cp << 12) + i4;
    *(uint4*)&g_AFph[o] = hq;
    *(uint4*)&g_AFpl[o] = lq;
}

// ---------------- fuse GEMM tensor cores: K=512, scatter out --------------
__global__ __launch_bounds__(256) void k_fuse_tc(float* __restrict__ out) {
    int b = blockIdx.z;
    int m0 = blockIdx.y << 7;
    int n0 = blockIdx.x << 7;
    int nq = g_nq[b];
    if (n0 >= PAD128(nq)) return;
    __shared__ uint32_t sWh[128 * 9], sWl[128 * 9];
    __shared__ uint32_t sFh[8 * 136], sFl[8 * 136];
    int tid = threadIdx.x;
    int w = tid >> 5, l = tid & 31;
    int wm = w & 3, wn = w >> 2;
    int grp = l >> 2, tig = l & 3;
    int q = tid & 127, half = tid >> 7;
    long fbase = ((long)b << 19);

    float acc[2][8][4];
#pragma unroll
    for (int i = 0; i < 2; i++)
#pragma unroll
        for (int j = 0; j < 8; j++)
#pragma unroll
            for (int k = 0; k < 4; k++) acc[i][j][k] = 0.f;

    for (int step = 0; step < 32; step++) {
        int c0p = step << 3;
#pragma unroll
        for (int it = 0; it < 4; it++) {
            int cp = (it << 1) + half;
            int cpg = c0p + cp;
            sWh[q * 9 + cp] = g_WFh[cpg * 256 + m0 + q];
            sWl[q * 9 + cp] = g_WFl[cpg * 256 + m0 + q];
            const uint32_t* Fh = (cpg < 128) ? g_AFph : g_Xqph;
            const uint32_t* Fl = (cpg < 128) ? g_AFpl : g_Xqpl;
            long g = fbase + ((long)(cpg & 127) << 12);
            sFh[cp * 136 + q] = Fh[g + n0 + q];
            sFl[cp * 136 + q] = Fl[g + n0 + q];
        }
        __syncthreads();
        uint32_t ah[2][4], al[2][4];
#pragma unroll
        for (int mf = 0; mf < 2; mf++) {
            int ab = ((wm << 5) + (mf << 4) + grp) * 9;
            ah[mf][0] = sWh[ab + tig];
            ah[mf][1] = sWh[ab + 72 + tig];
            ah[mf][2] = sWh[ab + tig + 4];
            ah[mf][3] = sWh[ab + 72 + tig + 4];
            al[mf][0] = sWl[ab + tig];
            al[mf][1] = sWl[ab + 72 + tig];
            al[mf][2] = sWl[ab + tig + 4];
            al[mf][3] = sWl[ab + 72 + tig + 4];
        }
#pragma unroll
        for (int nf = 0; nf < 8; nf++) {
            int n = (wn << 6) + (nf << 3) + grp;
            uint32_t bh0 = sFh[tig * 136 + n];
            uint32_t bh1 = sFh[(tig + 4) * 136 + n];
            uint32_t bl0 = sFl[tig * 136 + n];
            uint32_t bl1 = sFl[(tig + 4) * 136 + n];
#pragma unroll
            for (int mf = 0; mf < 2; mf++) {
                mma_bf16(acc[mf][nf], ah[mf], bh0, bh1);
                mma_bf16(acc[mf][nf], ah[mf], bl0, bl1);
                mma_bf16(acc[mf][nf], al[mf], bh0, bh1);
            }
        }
        __syncthreads();
    }
    const int* qidx = g_qidx + (b << 12);
#pragma unroll
    for (int mf = 0; mf < 2; mf++) {
        int r0 = m0 + (wm << 5) + (mf << 4) + grp;
#pragma unroll
        for (int nf = 0; nf < 8; nf++) {
            int cc = n0 + (wn << 6) + (nf << 3) + (tig << 1);
            if (cc < nq) {
                int px = qidx[cc];
                out[((b * CC + r0) << 12) + px] = acc[mf][nf][0];
                out[((b * CC + r0 + 8) << 12) + px] = acc[mf][nf][2];
            }
            if (cc + 1 < nq) {
                int px = qidx[cc + 1];
                out[((b * CC + r0) << 12) + px] = acc[mf][nf][1];
                out[((b * CC + r0 + 8) << 12) + px] = acc[mf][nf][3];
            }
        }
    }
}

// ---------------- global max of visatt ----------------------------------
__global__ void k_vismax() {
    float mx = -1e30f;
    for (int i = threadIdx.x; i < BB * NN; i += 256) mx = fmaxf(mx, g_vis[i]);
    mx = warpMax(mx);
    __shared__ float sh[8];
    if ((threadIdx.x & 31) == 0) sh[threadIdx.x >> 5] = mx;
    __syncthreads();
    if (threadIdx.x == 0) {
        float m2 = sh[0];
#pragma unroll
        for (int i = 1; i < 8; i++) m2 = fmaxf(m2, sh[i]);
        g_maxv[0] = m2;
    }
}

// ---------------- attmask --------------------------------------------------
__global__ void k_attmask(float* __restrict__ o) {
    int i = blockIdx.x * 256 + threadIdx.x;
    int b = i >> 18;
    int r = i & 262143;
    int Y = r >> 9, X = r & 511;
    o[i] = g_vis[(b << 12) + ((Y >> 3) << 6) + (X >> 3)] / g_maxv[0];
}

// ---------------- launch -------------------------------------------------
extern "C" void kernel_launch(void* const* d_in, const int* in_sizes, int n_in,
                              void* d_out, int out_size) {
    const float* x = nullptr;
    const float* mask = nullptr;
    const float* w1 = nullptr;
    const float* w2 = nullptr;
    const float* wf = nullptr;
    int seen589 = 0;
    for (int i = 0; i < n_in; i++) {
        switch (in_sizes[i]) {
            case 2097152: x = (const float*)d_in[i]; break;
            case 524288:  mask = (const float*)d_in[i]; break;
            case 589824:
                if (seen589++ == 0) w1 = (const float*)d_in[i];
                else w2 = (const float*)d_in[i];
                break;
            case 131072:  wf = (const float*)d_in[i]; break;
            default: break;
        }
    }

    float *bufA, *bufB, *Vc, *att;
    __nv_bfloat16 *xh, *xl, *f1h, *f1l;
    uint32_t *w1h, *w1l, *w2h, *w2l;
    cudaGetSymbolAddress((void**)&bufA, g_bufA);
    cudaGetSymbolAddress((void**)&bufB, g_bufB);
    cudaGetSymbolAddress((void**)&Vc, g_Vc);
    cudaGetSymbolAddress((void**)&att, g_att);
    cudaGetSymbolAddress((void**)&xh, g_xh);
    cudaGetSymbolAddress((void**)&xl, g_xl);
    cudaGetSymbolAddress((void**)&f1h, g_f1h);
    cudaGetSymbolAddress((void**)&f1l, g_f1l);
    cudaGetSymbolAddress((void**)&w1h, g_w1h);
    cudaGetSymbolAddress((void**)&w1l, g_w1l);
    cudaGetSymbolAddress((void**)&w2h, g_w2h);
    cudaGetSymbolAddress((void**)&w2l, g_w2l);

    static cudaStream_t s1 = nullptr;
    static cudaEvent_t ev0 = nullptr, ev1 = nullptr, ev2 = nullptr, ev3 = nullptr;
    static int smem_set = 0;
    const int CONV_SMEM = (13824 + 9216 + 1728 * 2) * 4;   // 105984 B
    if (!smem_set) {
        cudaFuncSetAttribute(k_conv_tc, cudaFuncAttributeMaxDynamicSharedMemorySize,
                             CONV_SMEM);
        cudaStreamCreateWithFlags(&s1, cudaStreamNonBlocking);
        cudaEventCreateWithFlags(&ev0, cudaEventDisableTiming);
        cudaEventCreateWithFlags(&ev1, cudaEventDisableTiming);
        cudaEventCreateWithFlags(&ev2, cudaEventDisableTiming);
        cudaEventCreateWithFlags(&ev3, cudaEventDisableTiming);
        smem_set = 1;
    }

    float* out = (float*)d_out;
    float* attm = out + (long)BB * CC * NN;

    // fork: side stream does memcpy + weight/input packing
    cudaEventRecord(ev0, 0);
    cudaStreamWaitEvent(s1, ev0, 0);
    cudaMemcpyAsync(out, x, (size_t)BB * CC * NN * sizeof(float),
                    cudaMemcpyDeviceToDevice, s1);
    k_packW<<<1152, 256, 0, s1>>>(w1, w1h, w1l);
    k_packW<<<1152, 256, 0, s1>>>(w2, w2h, w2l);
    k_packWF<<<256, 256, 0, s1>>>(wf);
    k_packX<<<8192, 256, 0, s1>>>(x, xh, xl);
    cudaEventRecord(ev1, s1);

    // main stream: mask/compact concurrently with the packing above
    k_mask<<<32, 256>>>(mask);
    k_compact<<<BB, 256>>>();
    cudaStreamWaitEvent(0, ev1, 0);

    k_conv_tc<<<dim3(64, 2, BB), 256, CONV_SMEM>>>(xh, xl, w1h, w1l, bufA);
    k_inorm0<<<BB * CC, 256>>>(bufA, f1h, f1l);
    k_conv_tc<<<dim3(64, 2, BB), 256, CONV_SMEM>>>(f1h, f1l, w2h, w2l, bufA);
    k_inorm1<<<BB * CC, 256>>>(bufA, x, bufB);            // bufB = feat
    k_gather<<<dim3(16, 2, BB), 256>>>(bufB, x);          // fused rn + pack
    k_score_tc<<<dim3(32, 32, BB), 256>>>(att);
    k_softmax<<<dim3(4096, BB), 256>>>(att);              // in-place fp32

    // fork: visatt chain + attmask on side stream, concurrent with av/fuse
    cudaEventRecord(ev2, 0);
    cudaStreamWaitEvent(s1, ev2, 0);
    k_visatt1<<<dim3(8, 32, BB), 256, 0, s1>>>(att);
    k_visatt2<<<dim3(8, BB), 256, 0, s1>>>();
    k_vismax<<<1, 256, 0, s1>>>();
    k_attmask<<<2048, 256, 0, s1>>>(attm);
    cudaEventRecord(ev3, s1);

    k_av_tc<<<dim3(32, 2, BB), 256>>>(Vc, att, bufA);     // bufA = att_fore
    k_packF<<<1024, 256>>>(bufA);
    k_fuse_tc<<<dim3(32, 2, BB), 256>>>(out);

    // join: attmask must complete before capture ends
    cudaStreamWaitEvent(0, ev3, 0);
}